// round 5
// baseline (speedup 1.0000x reference)
#include <cuda_runtime.h>
#include <cuda_bf16.h>
#include <math.h>
#include <stdint.h>

#define DIMV  1024
#define HEADS 16
#define BLKSZ 129
#define DK    64
#define BSZ   4
#define NB    32
#define NTOK  (BLKSZ * NB)      // 4128
#define MROWS (BSZ * NTOK)      // 16512

// fp32 scratch
__device__ float g_q[(size_t)MROWS * DIMV];
__device__ float g_k[(size_t)MROWS * DIMV];
__device__ float g_v[(size_t)MROWS * DIMV];
__device__ float g_gadd[(size_t)BSZ * HEADS * NB * DK];
// bf16 split scratch (x split, later reused for o split)
__device__ __nv_bfloat16 g_ah[(size_t)MROWS * DIMV];
__device__ __nv_bfloat16 g_al[(size_t)MROWS * DIMV];
__device__ __nv_bfloat16 g_wh[(size_t)DIMV * DIMV];
__device__ __nv_bfloat16 g_wl[(size_t)DIMV * DIMV];

// ---------------------------------------------------------------------------
// PTX helpers (all legal on compute_103 base target)
// ---------------------------------------------------------------------------
__device__ __forceinline__ uint32_t smem_u32(const void* p) {
    uint32_t a;
    asm("{ .reg .u64 t; cvta.to.shared.u64 t, %1; cvt.u32.u64 %0, t; }"
        : "=r"(a) : "l"(p));
    return a;
}
#define CP_ASYNC16(dst, src) \
    asm volatile("cp.async.cg.shared.global [%0], [%1], 16;" :: "r"(dst), "l"(src))
#define CP_COMMIT() asm volatile("cp.async.commit_group;")
#define CP_WAIT(n)  asm volatile("cp.async.wait_group %0;" :: "n"(n))

#define LDSM_X4(r0, r1, r2, r3, addr) \
    asm volatile("ldmatrix.sync.aligned.m8n8.x4.shared.b16 {%0,%1,%2,%3}, [%4];" \
        : "=r"(r0), "=r"(r1), "=r"(r2), "=r"(r3) : "r"(addr))

#define MMA16816(d, a, b) \
    asm volatile("mma.sync.aligned.m16n8k16.row.col.f32.bf16.bf16.f32 " \
        "{%0,%1,%2,%3}, {%4,%5,%6,%7}, {%8,%9}, {%0,%1,%2,%3};" \
        : "+f"((d)[0]), "+f"((d)[1]), "+f"((d)[2]), "+f"((d)[3]) \
        : "r"((a)[0]), "r"((a)[1]), "r"((a)[2]), "r"((a)[3]), \
          "r"((b)[0]), "r"((b)[1]))

// ---------------------------------------------------------------------------
// HMMA split-bf16 GEMM (unchanged from R3 passing kernel)
// ---------------------------------------------------------------------------
#define GK     1024
#define BKG    32
#define NKI    (GK / BKG)        // 32
#define TILE_B 8192              // 128 rows * 64B
#define SMEM_G (2 * 4 * TILE_B)  // 65536

__device__ __forceinline__ uint32_t sw_off(int row, int c) {
    int q = c ^ (row & 3) ^ ((row >> 2) & 1);
    return (uint32_t)(row * 64 + q * 16);
}

__device__ __forceinline__ void g_load_stage(
    uint32_t smem_base, int s, int k0, int m0, int n0, int tid,
    const __nv_bfloat16* __restrict__ Ah, const __nv_bfloat16* __restrict__ Al,
    const __nv_bfloat16* __restrict__ Bh, const __nv_bfloat16* __restrict__ Bl)
{
#pragma unroll
    for (int t = 0; t < 4; t++) {
        const __nv_bfloat16* base = (t == 0) ? Ah : (t == 1) ? Al : (t == 2) ? Bh : Bl;
        const int r0 = (t < 2) ? m0 : n0;
        const uint32_t tbase = smem_base + (uint32_t)(s * 4 + t) * TILE_B;
#pragma unroll
        for (int j = 0; j < 2; j++) {
            int idx = tid + j * 256;
            int row = idx >> 2, c = idx & 3;
            const void* src = base + (size_t)(r0 + row) * GK + k0 + c * 8;
            CP_ASYNC16(tbase + sw_off(row, c), src);
        }
    }
}

__global__ __launch_bounds__(256, 1)
void gemm_mma(const __nv_bfloat16* __restrict__ Ah, const __nv_bfloat16* __restrict__ Al,
              const __nv_bfloat16* __restrict__ Bh, const __nv_bfloat16* __restrict__ Bl,
              const float* __restrict__ bias, float* __restrict__ C, int Nn)
{
    extern __shared__ char smem[];
    const uint32_t smem_base = smem_u32(smem);
    const int tid = threadIdx.x;
    const int wid = tid >> 5, lid = tid & 31;
    const int warp_m = wid >> 2, warp_n = wid & 3;
    const int m0 = blockIdx.y * 128, n0 = blockIdx.x * 128;

    float acc[4][4][4];
#pragma unroll
    for (int i = 0; i < 4; i++)
#pragma unroll
        for (int j = 0; j < 4; j++)
#pragma unroll
            for (int f = 0; f < 4; f++) acc[i][j][f] = 0.0f;

    g_load_stage(smem_base, 0, 0,   m0, n0, tid, Ah, Al, Bh, Bl); CP_COMMIT();
    g_load_stage(smem_base, 1, BKG, m0, n0, tid, Ah, Al, Bh, Bl); CP_COMMIT();

    const int a_row = (lid & 15);
    const int a_chk = (lid >> 4) & 1;
    const int b_row = (lid & 7) + (((lid >> 4) & 1) << 3);
    const int b_chk = (lid >> 3) & 1;

    for (int ks = 0; ks < NKI; ks++) {
        if (ks + 1 < NKI) { CP_WAIT(1); } else { CP_WAIT(0); }
        __syncthreads();

        const int buf = ks & 1;
        const uint32_t bAh = smem_base + (uint32_t)(buf * 4 + 0) * TILE_B;
        const uint32_t bAl = smem_base + (uint32_t)(buf * 4 + 1) * TILE_B;
        const uint32_t bBh = smem_base + (uint32_t)(buf * 4 + 2) * TILE_B;
        const uint32_t bBl = smem_base + (uint32_t)(buf * 4 + 3) * TILE_B;

#pragma unroll
        for (int kk = 0; kk < BKG; kk += 16) {
            uint32_t ah[4][4], al[4][4], bh[4][2], bl[4][2];
            const int kc = kk >> 3;
#pragma unroll
            for (int i = 0; i < 4; i++) {
                int r = warp_m * 64 + i * 16 + a_row;
                uint32_t off = sw_off(r, kc + a_chk);
                LDSM_X4(ah[i][0], ah[i][1], ah[i][2], ah[i][3], bAh + off);
                LDSM_X4(al[i][0], al[i][1], al[i][2], al[i][3], bAl + off);
            }
#pragma unroll
            for (int j2 = 0; j2 < 2; j2++) {
                int r = warp_n * 32 + j2 * 16 + b_row;
                uint32_t off = sw_off(r, kc + b_chk);
                LDSM_X4(bh[j2 * 2][0], bh[j2 * 2][1], bh[j2 * 2 + 1][0], bh[j2 * 2 + 1][1],
                        bBh + off);
                LDSM_X4(bl[j2 * 2][0], bl[j2 * 2][1], bl[j2 * 2 + 1][0], bl[j2 * 2 + 1][1],
                        bBl + off);
            }
#pragma unroll
            for (int i = 0; i < 4; i++)
#pragma unroll
                for (int j = 0; j < 4; j++) {
                    MMA16816(acc[i][j], ah[i], bh[j]);
                    MMA16816(acc[i][j], ah[i], bl[j]);
                    MMA16816(acc[i][j], al[i], bh[j]);
                }
        }
        __syncthreads();
        if (ks + 2 < NKI) {
            g_load_stage(smem_base, buf, (ks + 2) * BKG, m0, n0, tid, Ah, Al, Bh, Bl);
            CP_COMMIT();
        }
    }

    const int g = lid >> 2, t = lid & 3;
#pragma unroll
    for (int i = 0; i < 4; i++) {
#pragma unroll
        for (int j = 0; j < 4; j++) {
            int row0 = m0 + warp_m * 64 + i * 16 + g;
            int col  = n0 + warp_n * 32 + j * 8 + 2 * t;
            float b0 = 0.f, b1 = 0.f;
            if (bias) { b0 = bias[col]; b1 = bias[col + 1]; }
            float2 v0 = make_float2(acc[i][j][0] + b0, acc[i][j][1] + b1);
            float2 v1 = make_float2(acc[i][j][2] + b0, acc[i][j][3] + b1);
            *(float2*)(C + (size_t)row0 * Nn + col)       = v0;
            *(float2*)(C + (size_t)(row0 + 8) * Nn + col) = v1;
        }
    }
}

// ---------------------------------------------------------------------------
// fp32 -> bf16 hi/lo split
// ---------------------------------------------------------------------------
__global__ __launch_bounds__(256)
void split_bf16(const float4* __restrict__ in, __nv_bfloat162* __restrict__ hi,
                __nv_bfloat162* __restrict__ lo, int n4)
{
    int i = blockIdx.x * 256 + threadIdx.x;
    if (i >= n4) return;
    float4 v = in[i];
    __nv_bfloat16 h0 = __float2bfloat16_rn(v.x), h1 = __float2bfloat16_rn(v.y);
    __nv_bfloat16 h2 = __float2bfloat16_rn(v.z), h3 = __float2bfloat16_rn(v.w);
    __nv_bfloat16 l0 = __float2bfloat16_rn(v.x - __bfloat162float(h0));
    __nv_bfloat16 l1 = __float2bfloat16_rn(v.y - __bfloat162float(h1));
    __nv_bfloat16 l2 = __float2bfloat16_rn(v.z - __bfloat162float(h2));
    __nv_bfloat16 l3 = __float2bfloat16_rn(v.w - __bfloat162float(h3));
    hi[2 * i]     = __nv_bfloat162(h0, h1);
    hi[2 * i + 1] = __nv_bfloat162(h2, h3);
    lo[2 * i]     = __nv_bfloat162(l0, l1);
    lo[2 * i + 1] = __nv_bfloat162(l2, l3);
}

// ---------------------------------------------------------------------------
// Global attention over the 32 block-start tokens per (b,h).
// Writes its contribution into g_gadd (consumed by attn_block2). Runs FIRST.
// ---------------------------------------------------------------------------
__global__ __launch_bounds__(32)
void attn_global(const float* __restrict__ Q, const float* __restrict__ Kt,
                 const float* __restrict__ Vt, float* __restrict__ gadd)
{
    __shared__ float Kg[NB * DK];
    __shared__ float Vg[NB * DK];
    const int h = blockIdx.x, b = blockIdx.y;
    const int tid = threadIdx.x;

    for (int i = tid; i < NB * DK; i += 32) {
        int j = i >> 6, d = i & 63;
        size_t r = ((size_t)(b * NTOK + j * BLKSZ)) * DIMV + h * DK + d;
        Kg[i] = Kt[r];
        Vg[i] = Vt[r];
    }
    __syncthreads();

    const int qj = tid;
    const size_t qbase = ((size_t)(b * NTOK + qj * BLKSZ)) * DIMV + h * DK;

    float qv[DK];
#pragma unroll
    for (int d = 0; d < DK; d++) qv[d] = Q[qbase + d];

    float s[NB];
    float m = -1e30f;
#pragma unroll
    for (int k = 0; k < NB; k++) {
        float dot = 0.0f;
#pragma unroll
        for (int d = 0; d < DK; d++) dot = fmaf(qv[d], Kg[k * DK + d], dot);
        s[k] = dot * 0.125f;
        m = fmaxf(m, s[k]);
    }
    float sum = 0.0f;
#pragma unroll
    for (int k = 0; k < NB; k++) { s[k] = __expf(s[k] - m); sum += s[k]; }
    float inv = 1.0f / sum;

    float acc[DK];
#pragma unroll
    for (int d = 0; d < DK; d++) acc[d] = 0.0f;
#pragma unroll
    for (int k = 0; k < NB; k++) {
        float p = s[k];
#pragma unroll
        for (int d = 0; d < DK; d++) acc[d] = fmaf(p, Vg[k * DK + d], acc[d]);
    }
    float* gp = gadd + (((size_t)(b * HEADS + h)) * NB + qj) * DK;
#pragma unroll
    for (int d = 0; d < DK; d++) gp[d] = acc[d] * inv;
}

// ---------------------------------------------------------------------------
// Flash-style block attention. One CTA per (blk,h,b). 2 threads per q row
// (each owns a 32-wide d-half; full dot via shfl_xor). Online softmax in
// chunks of 8 keys. Writes bf16 hi/lo of O directly (fused split), adding
// the global-attention contribution at the block-start row.
// ---------------------------------------------------------------------------
#define ATH2 288
#define ATTN2_SMEM (2 * BLKSZ * DK * sizeof(float))   // 66048

__global__ __launch_bounds__(ATH2, 2)
void attn_block2(const float* __restrict__ Q, const float* __restrict__ Kt,
                 const float* __restrict__ Vt, const float* __restrict__ gadd,
                 __nv_bfloat16* __restrict__ oh, __nv_bfloat16* __restrict__ ol)
{
    extern __shared__ float sm[];
    float* Ks = sm;                  // 129*64
    float* Vs = sm + BLKSZ * DK;     // 129*64

    const int blk = blockIdx.x, h = blockIdx.y, b = blockIdx.z;
    const int tid = threadIdx.x;
    const size_t base = ((size_t)(b * NTOK + blk * BLKSZ)) * DIMV + h * DK;

    for (int i = tid; i < BLKSZ * DK; i += ATH2) {
        int kk = i >> 6, d = i & 63;
        size_t src = base + (size_t)kk * DIMV + d;
        Ks[i] = Kt[src];
        Vs[i] = Vt[src];
    }
    __syncthreads();

    const int row  = tid >> 1;
    const int crow = row < BLKSZ ? row : BLKSZ - 1;   // clamp; extras discarded
    const int doff = (tid & 1) * 32;

    float4 qv[8];
    const float4* qp = (const float4*)(Q + base + (size_t)crow * DIMV + doff);
#pragma unroll
    for (int i = 0; i < 8; i++) qv[i] = qp[i];

    float4 acc[8];
#pragma unroll
    for (int i = 0; i < 8; i++) acc[i] = make_float4(0.f, 0.f, 0.f, 0.f);
    float m = -1e30f, l = 0.0f;

    for (int k0 = 0; k0 < BLKSZ; k0 += 8) {
        float s[8];
#pragma unroll
        for (int j = 0; j < 8; j++) {
            int k = k0 + j;
            int kc = k < BLKSZ ? k : BLKSZ - 1;
            const float4* kr = (const float4*)(Ks + kc * DK + doff);
            float p = 0.0f;
#pragma unroll
            for (int i = 0; i < 8; i++) {
                float4 kv = kr[i];
                p = fmaf(qv[i].x, kv.x, p); p = fmaf(qv[i].y, kv.y, p);
                p = fmaf(qv[i].z, kv.z, p); p = fmaf(qv[i].w, kv.w, p);
            }
            p += __shfl_xor_sync(0xFFFFFFFF, p, 1);
            s[j] = (k < BLKSZ) ? p * 0.125f : -1e30f;
        }

        float cm = s[0];
#pragma unroll
        for (int j = 1; j < 8; j++) cm = fmaxf(cm, s[j]);
        float nm = fmaxf(m, cm);
        float corr = __expf(m - nm);
        l *= corr;
#pragma unroll
        for (int i = 0; i < 8; i++) {
            acc[i].x *= corr; acc[i].y *= corr;
            acc[i].z *= corr; acc[i].w *= corr;
        }
#pragma unroll
        for (int j = 0; j < 8; j++) {
            int k = k0 + j;
            int kc = k < BLKSZ ? k : BLKSZ - 1;
            float p = __expf(s[j] - nm);
            l += p;
            const float4* vr = (const float4*)(Vs + kc * DK + doff);
#pragma unroll
            for (int i = 0; i < 8; i++) {
                float4 vv = vr[i];
                acc[i].x = fmaf(p, vv.x, acc[i].x);
                acc[i].y = fmaf(p, vv.y, acc[i].y);
                acc[i].z = fmaf(p, vv.z, acc[i].z);
                acc[i].w = fmaf(p, vv.w, acc[i].w);
            }
        }
        m = nm;
    }

    if (row < BLKSZ) {
        const float inv = 1.0f / l;
        const bool add_g = (row == 0);
        const float* ga = gadd + (((size_t)(b * HEADS + h)) * NB + blk) * DK + doff;
        const size_t obase = base + (size_t)row * DIMV + doff;
#pragma unroll
        for (int i = 0; i < 8; i++) {
            float4 r = acc[i];
            r.x *= inv; r.y *= inv; r.z *= inv; r.w *= inv;
            if (add_g) {
                r.x += ga[4 * i + 0]; r.y += ga[4 * i + 1];
                r.z += ga[4 * i + 2]; r.w += ga[4 * i + 3];
            }
            __nv_bfloat16 h0 = __float2bfloat16_rn(r.x), h1 = __float2bfloat16_rn(r.y);
            __nv_bfloat16 h2 = __float2bfloat16_rn(r.z), h3 = __float2bfloat16_rn(r.w);
            __nv_bfloat16 l0 = __float2bfloat16_rn(r.x - __bfloat162float(h0));
            __nv_bfloat16 l1 = __float2bfloat16_rn(r.y - __bfloat162float(h1));
            __nv_bfloat16 l2 = __float2bfloat16_rn(r.z - __bfloat162float(h2));
            __nv_bfloat16 l3 = __float2bfloat16_rn(r.w - __bfloat162float(h3));
            *(__nv_bfloat162*)(oh + obase + 4 * i)     = __nv_bfloat162(h0, h1);
            *(__nv_bfloat162*)(oh + obase + 4 * i + 2) = __nv_bfloat162(h2, h3);
            *(__nv_bfloat162*)(ol + obase + 4 * i)     = __nv_bfloat162(l0, l1);
            *(__nv_bfloat162*)(ol + obase + 4 * i + 2) = __nv_bfloat162(l2, l3);
        }
    }
}

// ---------------------------------------------------------------------------
extern "C" void kernel_launch(void* const* d_in, const int* in_sizes, int n_in,
                              void* d_out, int out_size)
{
    const float* x  = (const float*)d_in[0];
    const float* Wq = (const float*)d_in[1];
    const float* Wk = (const float*)d_in[2];
    const float* Wv = (const float*)d_in[3];
    const float* Wo = (const float*)d_in[4];
    const float* bo = (const float*)d_in[5];
    float* out = (float*)d_out;

    float *q, *k, *v, *gadd;
    __nv_bfloat16 *ah, *al, *wh, *wl;
    cudaGetSymbolAddress((void**)&q, g_q);
    cudaGetSymbolAddress((void**)&k, g_k);
    cudaGetSymbolAddress((void**)&v, g_v);
    cudaGetSymbolAddress((void**)&gadd, g_gadd);
    cudaGetSymbolAddress((void**)&ah, g_ah);
    cudaGetSymbolAddress((void**)&al, g_al);
    cudaGetSymbolAddress((void**)&wh, g_wh);
    cudaGetSymbolAddress((void**)&wl, g_wl);

    cudaFuncSetAttribute(attn_block2, cudaFuncAttributeMaxDynamicSharedMemorySize,
                         (int)ATTN2_SMEM);
    cudaFuncSetAttribute(gemm_mma, cudaFuncAttributeMaxDynamicSharedMemorySize,
                         SMEM_G);

    const int nX4 = MROWS * DIMV / 4;
    const int nW4 = DIMV * DIMV / 4;
    dim3 ggrid(DIMV / 128, MROWS / 128);   // (8, 129)

    split_bf16<<<(nX4 + 255) / 256, 256>>>((const float4*)x,
        (__nv_bfloat162*)ah, (__nv_bfloat162*)al, nX4);

    split_bf16<<<(nW4 + 255) / 256, 256>>>((const float4*)Wq,
        (__nv_bfloat162*)wh, (__nv_bfloat162*)wl, nW4);
    gemm_mma<<<ggrid, 256, SMEM_G>>>(ah, al, wh, wl, nullptr, q, DIMV);

    split_bf16<<<(nW4 + 255) / 256, 256>>>((const float4*)Wk,
        (__nv_bfloat162*)wh, (__nv_bfloat162*)wl, nW4);
    gemm_mma<<<ggrid, 256, SMEM_G>>>(ah, al, wh, wl, nullptr, k, DIMV);

    split_bf16<<<(nW4 + 255) / 256, 256>>>((const float4*)Wv,
        (__nv_bfloat162*)wh, (__nv_bfloat162*)wl, nW4);
    gemm_mma<<<ggrid, 256, SMEM_G>>>(ah, al, wh, wl, nullptr, v, DIMV);

    attn_global<<<dim3(HEADS, BSZ), 32>>>(q, k, v, gadd);
    // attn_block2 overwrites ah/al (x split no longer needed) with o's split
    attn_block2<<<dim3(NB, HEADS, BSZ), ATH2, ATTN2_SMEM>>>(q, k, v, gadd, ah, al);

    split_bf16<<<(nW4 + 255) / 256, 256>>>((const float4*)Wo,
        (__nv_bfloat162*)wh, (__nv_bfloat162*)wl, nW4);
    gemm_mma<<<ggrid, 256, SMEM_G>>>(ah, al, wh, wl, bo, out, DIMV);
}

// round 6
// speedup vs baseline: 1.0359x; 1.0359x over previous
#include <cuda_runtime.h>
#include <cuda_bf16.h>
#include <math.h>
#include <stdint.h>

#define DIMV  1024
#define HEADS 16
#define BLKSZ 129
#define DK    64
#define BSZ   4
#define NB    32
#define NTOK  (BLKSZ * NB)      // 4128
#define MROWS (BSZ * NTOK)      // 16512

// fp32 scratch
__device__ float g_q[(size_t)MROWS * DIMV];
__device__ float g_k[(size_t)MROWS * DIMV];
__device__ float g_v[(size_t)MROWS * DIMV];
__device__ float g_gadd[(size_t)BSZ * HEADS * NB * DK];
// bf16 split scratch (x split, later reused for o split)
__device__ __nv_bfloat16 g_ah[(size_t)MROWS * DIMV];
__device__ __nv_bfloat16 g_al[(size_t)MROWS * DIMV];
__device__ __nv_bfloat16 g_wh[(size_t)DIMV * DIMV];
__device__ __nv_bfloat16 g_wl[(size_t)DIMV * DIMV];

// ---------------------------------------------------------------------------
// PTX helpers (all legal on compute_103 base target)
// ---------------------------------------------------------------------------
__device__ __forceinline__ uint32_t smem_u32(const void* p) {
    uint32_t a;
    asm("{ .reg .u64 t; cvta.to.shared.u64 t, %1; cvt.u32.u64 %0, t; }"
        : "=r"(a) : "l"(p));
    return a;
}
#define CP_ASYNC16(dst, src) \
    asm volatile("cp.async.cg.shared.global [%0], [%1], 16;" :: "r"(dst), "l"(src))
#define CP_COMMIT() asm volatile("cp.async.commit_group;")
#define CP_WAIT(n)  asm volatile("cp.async.wait_group %0;" :: "n"(n))

#define LDSM_X4(r0, r1, r2, r3, addr) \
    asm volatile("ldmatrix.sync.aligned.m8n8.x4.shared.b16 {%0,%1,%2,%3}, [%4];" \
        : "=r"(r0), "=r"(r1), "=r"(r2), "=r"(r3) : "r"(addr))

#define MMA16816(d, a, b) \
    asm volatile("mma.sync.aligned.m16n8k16.row.col.f32.bf16.bf16.f32 " \
        "{%0,%1,%2,%3}, {%4,%5,%6,%7}, {%8,%9}, {%0,%1,%2,%3};" \
        : "+f"((d)[0]), "+f"((d)[1]), "+f"((d)[2]), "+f"((d)[3]) \
        : "r"((a)[0]), "r"((a)[1]), "r"((a)[2]), "r"((a)[3]), \
          "r"((b)[0]), "r"((b)[1]))

// ---------------------------------------------------------------------------
// HMMA split-bf16 GEMM:  C[M,Nn] = A @ W^T (+bias), fp32 out
// CTA tile 128x128x32, 8 warps (2x4 -> 64x32 warp tile).
// 3 smem buffers: load for stage ks+2 issued BEFORE compute of stage ks
// (into the buffer freed at stage ks-1), one __syncthreads per K-iter.
// ---------------------------------------------------------------------------
#define GK     1024
#define BKG    32
#define NKI    (GK / BKG)        // 32
#define TILE_B 8192              // 128 rows * 64B
#define SMEM_G (3 * 4 * TILE_B)  // 98304

__device__ __forceinline__ uint32_t sw_off(int row, int c) {
    int q = c ^ (row & 3) ^ ((row >> 2) & 1);
    return (uint32_t)(row * 64 + q * 16);
}

__device__ __forceinline__ void g_load_stage(
    uint32_t smem_base, int s, int k0, int m0, int n0, int tid,
    const __nv_bfloat16* __restrict__ Ah, const __nv_bfloat16* __restrict__ Al,
    const __nv_bfloat16* __restrict__ Bh, const __nv_bfloat16* __restrict__ Bl)
{
#pragma unroll
    for (int t = 0; t < 4; t++) {
        const __nv_bfloat16* base = (t == 0) ? Ah : (t == 1) ? Al : (t == 2) ? Bh : Bl;
        const int r0 = (t < 2) ? m0 : n0;
        const uint32_t tbase = smem_base + (uint32_t)(s * 4 + t) * TILE_B;
#pragma unroll
        for (int j = 0; j < 2; j++) {
            int idx = tid + j * 256;
            int row = idx >> 2, c = idx & 3;
            const void* src = base + (size_t)(r0 + row) * GK + k0 + c * 8;
            CP_ASYNC16(tbase + sw_off(row, c), src);
        }
    }
}

__global__ __launch_bounds__(256, 1)
void gemm_mma(const __nv_bfloat16* __restrict__ Ah, const __nv_bfloat16* __restrict__ Al,
              const __nv_bfloat16* __restrict__ Bh, const __nv_bfloat16* __restrict__ Bl,
              const float* __restrict__ bias, float* __restrict__ C, int Nn)
{
    extern __shared__ char smem[];
    const uint32_t smem_base = smem_u32(smem);
    const int tid = threadIdx.x;
    const int wid = tid >> 5, lid = tid & 31;
    const int warp_m = wid >> 2, warp_n = wid & 3;
    const int m0 = blockIdx.y * 128, n0 = blockIdx.x * 128;

    float acc[4][4][4];
#pragma unroll
    for (int i = 0; i < 4; i++)
#pragma unroll
        for (int j = 0; j < 4; j++)
#pragma unroll
            for (int f = 0; f < 4; f++) acc[i][j][f] = 0.0f;

    g_load_stage(smem_base, 0, 0,   m0, n0, tid, Ah, Al, Bh, Bl); CP_COMMIT();
    g_load_stage(smem_base, 1, BKG, m0, n0, tid, Ah, Al, Bh, Bl); CP_COMMIT();

    const int a_row = (lid & 15);
    const int a_chk = (lid >> 4) & 1;
    const int b_row = (lid & 7) + (((lid >> 4) & 1) << 3);
    const int b_chk = (lid >> 3) & 1;

    for (int ks = 0; ks < NKI; ks++) {
        if (ks + 1 < NKI) { CP_WAIT(1); } else { CP_WAIT(0); }
        __syncthreads();

        // issue next-next load into the buffer freed at stage ks-1
        if (ks + 2 < NKI) {
            g_load_stage(smem_base, (ks + 2) % 3, (ks + 2) * BKG, m0, n0, tid,
                         Ah, Al, Bh, Bl);
            CP_COMMIT();
        }

        const int buf = ks % 3;
        const uint32_t bAh = smem_base + (uint32_t)(buf * 4 + 0) * TILE_B;
        const uint32_t bAl = smem_base + (uint32_t)(buf * 4 + 1) * TILE_B;
        const uint32_t bBh = smem_base + (uint32_t)(buf * 4 + 2) * TILE_B;
        const uint32_t bBl = smem_base + (uint32_t)(buf * 4 + 3) * TILE_B;

#pragma unroll
        for (int kk = 0; kk < BKG; kk += 16) {
            uint32_t ah[4][4], al[4][4], bh[4][2], bl[4][2];
            const int kc = kk >> 3;
#pragma unroll
            for (int i = 0; i < 4; i++) {
                int r = warp_m * 64 + i * 16 + a_row;
                uint32_t off = sw_off(r, kc + a_chk);
                LDSM_X4(ah[i][0], ah[i][1], ah[i][2], ah[i][3], bAh + off);
                LDSM_X4(al[i][0], al[i][1], al[i][2], al[i][3], bAl + off);
            }
#pragma unroll
            for (int j2 = 0; j2 < 2; j2++) {
                int r = warp_n * 32 + j2 * 16 + b_row;
                uint32_t off = sw_off(r, kc + b_chk);
                LDSM_X4(bh[j2 * 2][0], bh[j2 * 2][1], bh[j2 * 2 + 1][0], bh[j2 * 2 + 1][1],
                        bBh + off);
                LDSM_X4(bl[j2 * 2][0], bl[j2 * 2][1], bl[j2 * 2 + 1][0], bl[j2 * 2 + 1][1],
                        bBl + off);
            }
#pragma unroll
            for (int i = 0; i < 4; i++)
#pragma unroll
                for (int j = 0; j < 4; j++) {
                    MMA16816(acc[i][j], ah[i], bh[j]);
                    MMA16816(acc[i][j], ah[i], bl[j]);
                    MMA16816(acc[i][j], al[i], bh[j]);
                }
        }
    }

    const int g = lid >> 2, t = lid & 3;
#pragma unroll
    for (int i = 0; i < 4; i++) {
#pragma unroll
        for (int j = 0; j < 4; j++) {
            int row0 = m0 + warp_m * 64 + i * 16 + g;
            int col  = n0 + warp_n * 32 + j * 8 + 2 * t;
            float b0 = 0.f, b1 = 0.f;
            if (bias) { b0 = bias[col]; b1 = bias[col + 1]; }
            float2 v0 = make_float2(acc[i][j][0] + b0, acc[i][j][1] + b1);
            float2 v1 = make_float2(acc[i][j][2] + b0, acc[i][j][3] + b1);
            *(float2*)(C + (size_t)row0 * Nn + col)       = v0;
            *(float2*)(C + (size_t)(row0 + 8) * Nn + col) = v1;
        }
    }
}

// ---------------------------------------------------------------------------
// fp32 -> bf16 hi/lo split
// ---------------------------------------------------------------------------
__global__ __launch_bounds__(256)
void split_bf16(const float4* __restrict__ in, __nv_bfloat162* __restrict__ hi,
                __nv_bfloat162* __restrict__ lo, int n4)
{
    int i = blockIdx.x * 256 + threadIdx.x;
    if (i >= n4) return;
    float4 v = in[i];
    __nv_bfloat16 h0 = __float2bfloat16_rn(v.x), h1 = __float2bfloat16_rn(v.y);
    __nv_bfloat16 h2 = __float2bfloat16_rn(v.z), h3 = __float2bfloat16_rn(v.w);
    __nv_bfloat16 l0 = __float2bfloat16_rn(v.x - __bfloat162float(h0));
    __nv_bfloat16 l1 = __float2bfloat16_rn(v.y - __bfloat162float(h1));
    __nv_bfloat16 l2 = __float2bfloat16_rn(v.z - __bfloat162float(h2));
    __nv_bfloat16 l3 = __float2bfloat16_rn(v.w - __bfloat162float(h3));
    hi[2 * i]     = __nv_bfloat162(h0, h1);
    hi[2 * i + 1] = __nv_bfloat162(h2, h3);
    lo[2 * i]     = __nv_bfloat162(l0, l1);
    lo[2 * i + 1] = __nv_bfloat162(l2, l3);
}

// ---------------------------------------------------------------------------
// Global attention over the 32 block-start tokens per (b,h).
// Writes its contribution into g_gadd (consumed by attn_block). Runs FIRST.
// ---------------------------------------------------------------------------
__global__ __launch_bounds__(32)
void attn_global(const float* __restrict__ Q, const float* __restrict__ Kt,
                 const float* __restrict__ Vt, float* __restrict__ gadd)
{
    __shared__ float Kg[NB * DK];
    __shared__ float Vg[NB * DK];
    const int h = blockIdx.x, b = blockIdx.y;
    const int tid = threadIdx.x;

    for (int i = tid; i < NB * DK; i += 32) {
        int j = i >> 6, d = i & 63;
        size_t r = ((size_t)(b * NTOK + j * BLKSZ)) * DIMV + h * DK + d;
        Kg[i] = Kt[r];
        Vg[i] = Vt[r];
    }
    __syncthreads();

    const int qj = tid;
    const size_t qbase = ((size_t)(b * NTOK + qj * BLKSZ)) * DIMV + h * DK;

    float qv[DK];
#pragma unroll
    for (int d = 0; d < DK; d++) qv[d] = Q[qbase + d];

    float s[NB];
    float m = -1e30f;
#pragma unroll
    for (int k = 0; k < NB; k++) {
        float dot = 0.0f;
#pragma unroll
        for (int d = 0; d < DK; d++) dot = fmaf(qv[d], Kg[k * DK + d], dot);
        s[k] = dot * 0.125f;
        m = fmaxf(m, s[k]);
    }
    float sum = 0.0f;
#pragma unroll
    for (int k = 0; k < NB; k++) { s[k] = __expf(s[k] - m); sum += s[k]; }
    float inv = 1.0f / sum;

    float acc[DK];
#pragma unroll
    for (int d = 0; d < DK; d++) acc[d] = 0.0f;
#pragma unroll
    for (int k = 0; k < NB; k++) {
        float p = s[k];
#pragma unroll
        for (int d = 0; d < DK; d++) acc[d] = fmaf(p, Vg[k * DK + d], acc[d]);
    }
    float* gp = gadd + (((size_t)(b * HEADS + h)) * NB + qj) * DK;
#pragma unroll
    for (int d = 0; d < DK; d++) gp[d] = acc[d] * inv;
}

// ---------------------------------------------------------------------------
// Block attention (R1/R3 proven two-pass structure) with fused bf16 hi/lo
// output split and global-attention add at the block-start row.
// ---------------------------------------------------------------------------
#define ATH 160
#define SC_LD 133
#define ATTN_SMEM ((BLKSZ * DK + BLKSZ * SC_LD) * sizeof(float))

__global__ __launch_bounds__(ATH)
void attn_block(const float* __restrict__ Q, const float* __restrict__ Kt,
                const float* __restrict__ Vt, const float* __restrict__ gadd,
                __nv_bfloat16* __restrict__ ohi, __nv_bfloat16* __restrict__ olo)
{
    extern __shared__ float sm[];
    float* Ks = sm;
    float* sc = sm + BLKSZ * DK;

    const int blk = blockIdx.x, h = blockIdx.y, b = blockIdx.z;
    const int tid = threadIdx.x;
    const size_t base = ((size_t)(b * NTOK + blk * BLKSZ)) * DIMV + h * DK;

    for (int i = tid; i < BLKSZ * DK; i += ATH) {
        int kk = i >> 6, d = i & 63;
        Ks[i] = Kt[base + (size_t)kk * DIMV + d];
    }
    __syncthreads();

    const int q = tid;
    float4 qv[16];
    if (q < BLKSZ) {
        const float4* qp = (const float4*)(Q + base + (size_t)q * DIMV);
#pragma unroll
        for (int i = 0; i < 16; i++) qv[i] = qp[i];
        float* srow = sc + q * SC_LD;
        for (int k = 0; k < BLKSZ; k++) {
            const float4* kr = (const float4*)(Ks + k * DK);
            float s = 0.0f;
#pragma unroll
            for (int i = 0; i < 16; i++) {
                float4 kv = kr[i];
                s = fmaf(qv[i].x, kv.x, s); s = fmaf(qv[i].y, kv.y, s);
                s = fmaf(qv[i].z, kv.z, s); s = fmaf(qv[i].w, kv.w, s);
            }
            srow[k] = s * 0.125f;
        }
    }
    __syncthreads();

    for (int i = tid; i < BLKSZ * DK; i += ATH) {
        int kk = i >> 6, d = i & 63;
        Ks[i] = Vt[base + (size_t)kk * DIMV + d];
    }

    float inv = 0.0f;
    if (q < BLKSZ) {
        float* srow = sc + q * SC_LD;
        float m = -1e30f;
        for (int k = 0; k < BLKSZ; k++) m = fmaxf(m, srow[k]);
        float sum = 0.0f;
        for (int k = 0; k < BLKSZ; k++) {
            float e = __expf(srow[k] - m);
            srow[k] = e;
            sum += e;
        }
        inv = 1.0f / sum;
    }
    __syncthreads();

    if (q < BLKSZ) {
        float4 accv[16];
#pragma unroll
        for (int i = 0; i < 16; i++) accv[i] = make_float4(0.f, 0.f, 0.f, 0.f);
        float* srow = sc + q * SC_LD;
        for (int k = 0; k < BLKSZ; k++) {
            float p = srow[k];
            const float4* vr = (const float4*)(Ks + k * DK);
#pragma unroll
            for (int i = 0; i < 16; i++) {
                float4 vv = vr[i];
                accv[i].x = fmaf(p, vv.x, accv[i].x);
                accv[i].y = fmaf(p, vv.y, accv[i].y);
                accv[i].z = fmaf(p, vv.z, accv[i].z);
                accv[i].w = fmaf(p, vv.w, accv[i].w);
            }
        }
        const bool add_g = (q == 0);
        const float* ga = gadd + (((size_t)(b * HEADS + h)) * NB + blk) * DK;
        const size_t obase = base + (size_t)q * DIMV;
#pragma unroll
        for (int i = 0; i < 16; i++) {
            float4 r = accv[i];
            r.x *= inv; r.y *= inv; r.z *= inv; r.w *= inv;
            if (add_g) {
                r.x += ga[4 * i + 0]; r.y += ga[4 * i + 1];
                r.z += ga[4 * i + 2]; r.w += ga[4 * i + 3];
            }
            __nv_bfloat16 h0 = __float2bfloat16_rn(r.x), h1 = __float2bfloat16_rn(r.y);
            __nv_bfloat16 h2 = __float2bfloat16_rn(r.z), h3 = __float2bfloat16_rn(r.w);
            __nv_bfloat16 l0 = __float2bfloat16_rn(r.x - __bfloat162float(h0));
            __nv_bfloat16 l1 = __float2bfloat16_rn(r.y - __bfloat162float(h1));
            __nv_bfloat16 l2 = __float2bfloat16_rn(r.z - __bfloat162float(h2));
            __nv_bfloat16 l3 = __float2bfloat16_rn(r.w - __bfloat162float(h3));
            *(__nv_bfloat162*)(ohi + obase + 4 * i)     = __nv_bfloat162(h0, h1);
            *(__nv_bfloat162*)(ohi + obase + 4 * i + 2) = __nv_bfloat162(h2, h3);
            *(__nv_bfloat162*)(olo + obase + 4 * i)     = __nv_bfloat162(l0, l1);
            *(__nv_bfloat162*)(olo + obase + 4 * i + 2) = __nv_bfloat162(l2, l3);
        }
    }
}

// ---------------------------------------------------------------------------
extern "C" void kernel_launch(void* const* d_in, const int* in_sizes, int n_in,
                              void* d_out, int out_size)
{
    const float* x  = (const float*)d_in[0];
    const float* Wq = (const float*)d_in[1];
    const float* Wk = (const float*)d_in[2];
    const float* Wv = (const float*)d_in[3];
    const float* Wo = (const float*)d_in[4];
    const float* bo = (const float*)d_in[5];
    float* out = (float*)d_out;

    float *q, *k, *v, *gadd;
    __nv_bfloat16 *ah, *al, *wh, *wl;
    cudaGetSymbolAddress((void**)&q, g_q);
    cudaGetSymbolAddress((void**)&k, g_k);
    cudaGetSymbolAddress((void**)&v, g_v);
    cudaGetSymbolAddress((void**)&gadd, g_gadd);
    cudaGetSymbolAddress((void**)&ah, g_ah);
    cudaGetSymbolAddress((void**)&al, g_al);
    cudaGetSymbolAddress((void**)&wh, g_wh);
    cudaGetSymbolAddress((void**)&wl, g_wl);

    cudaFuncSetAttribute(attn_block, cudaFuncAttributeMaxDynamicSharedMemorySize,
                         (int)ATTN_SMEM);
    cudaFuncSetAttribute(gemm_mma, cudaFuncAttributeMaxDynamicSharedMemorySize,
                         SMEM_G);

    const int nX4 = MROWS * DIMV / 4;
    const int nW4 = DIMV * DIMV / 4;
    dim3 ggrid(DIMV / 128, MROWS / 128);   // (8, 129)

    split_bf16<<<(nX4 + 255) / 256, 256>>>((const float4*)x,
        (__nv_bfloat162*)ah, (__nv_bfloat162*)al, nX4);

    split_bf16<<<(nW4 + 255) / 256, 256>>>((const float4*)Wq,
        (__nv_bfloat162*)wh, (__nv_bfloat162*)wl, nW4);
    gemm_mma<<<ggrid, 256, SMEM_G>>>(ah, al, wh, wl, nullptr, q, DIMV);

    split_bf16<<<(nW4 + 255) / 256, 256>>>((const float4*)Wk,
        (__nv_bfloat162*)wh, (__nv_bfloat162*)wl, nW4);
    gemm_mma<<<ggrid, 256, SMEM_G>>>(ah, al, wh, wl, nullptr, k, DIMV);

    split_bf16<<<(nW4 + 255) / 256, 256>>>((const float4*)Wv,
        (__nv_bfloat162*)wh, (__nv_bfloat162*)wl, nW4);
    gemm_mma<<<ggrid, 256, SMEM_G>>>(ah, al, wh, wl, nullptr, v, DIMV);

    attn_global<<<dim3(HEADS, BSZ), 32>>>(q, k, v, gadd);
    // attn_block overwrites ah/al (x split no longer needed) with o's split
    attn_block<<<dim3(NB, HEADS, BSZ), ATH, ATTN_SMEM>>>(q, k, v, gadd, ah, al);

    split_bf16<<<(nW4 + 255) / 256, 256>>>((const float4*)Wo,
        (__nv_bfloat162*)wh, (__nv_bfloat162*)wl, nW4);
    gemm_mma<<<ggrid, 256, SMEM_G>>>(ah, al, wh, wl, bo, out, DIMV);
}

// round 7
// speedup vs baseline: 1.0698x; 1.0327x over previous
#include <cuda_runtime.h>
#include <cuda_bf16.h>
#include <math.h>
#include <stdint.h>

#define DIMV  1024
#define HEADS 16
#define BLKSZ 129
#define DK    64
#define BSZ   4
#define NB    32
#define NTOK  (BLKSZ * NB)      // 4128
#define MROWS (BSZ * NTOK)      // 16512

// fp32 scratch
__device__ float g_q[(size_t)MROWS * DIMV];
__device__ float g_k[(size_t)MROWS * DIMV];
__device__ float g_v[(size_t)MROWS * DIMV];
__device__ float g_gadd[(size_t)BSZ * HEADS * NB * DK];
// bf16 split scratch
__device__ __nv_bfloat16 g_ah[(size_t)MROWS * DIMV];   // x split, then o split
__device__ __nv_bfloat16 g_al[(size_t)MROWS * DIMV];
__device__ __nv_bfloat16 g_wh[(size_t)DIMV * DIMV];    // Wq/Wk/Wv (sequential reuse not possible now) -> see g_w*2
__device__ __nv_bfloat16 g_wl[(size_t)DIMV * DIMV];
__device__ __nv_bfloat16 g_wh2[(size_t)DIMV * DIMV];
__device__ __nv_bfloat16 g_wl2[(size_t)DIMV * DIMV];
__device__ __nv_bfloat16 g_wh3[(size_t)DIMV * DIMV];
__device__ __nv_bfloat16 g_wl3[(size_t)DIMV * DIMV];
__device__ __nv_bfloat16 g_woh[(size_t)DIMV * DIMV];
__device__ __nv_bfloat16 g_wol[(size_t)DIMV * DIMV];

// ---------------------------------------------------------------------------
// PTX helpers (all legal on compute_103 base target)
// ---------------------------------------------------------------------------
__device__ __forceinline__ uint32_t smem_u32(const void* p) {
    uint32_t a;
    asm("{ .reg .u64 t; cvta.to.shared.u64 t, %1; cvt.u32.u64 %0, t; }"
        : "=r"(a) : "l"(p));
    return a;
}
#define CP_ASYNC16(dst, src) \
    asm volatile("cp.async.cg.shared.global [%0], [%1], 16;" :: "r"(dst), "l"(src))
#define CP_COMMIT() asm volatile("cp.async.commit_group;")
#define CP_WAIT(n)  asm volatile("cp.async.wait_group %0;" :: "n"(n))

#define LDSM_X4(r0, r1, r2, r3, addr) \
    asm volatile("ldmatrix.sync.aligned.m8n8.x4.shared.b16 {%0,%1,%2,%3}, [%4];" \
        : "=r"(r0), "=r"(r1), "=r"(r2), "=r"(r3) : "r"(addr))

#define MMA16816(d, a, b) \
    asm volatile("mma.sync.aligned.m16n8k16.row.col.f32.bf16.bf16.f32 " \
        "{%0,%1,%2,%3}, {%4,%5,%6,%7}, {%8,%9}, {%0,%1,%2,%3};" \
        : "+f"((d)[0]), "+f"((d)[1]), "+f"((d)[2]), "+f"((d)[3]) \
        : "r"((a)[0]), "r"((a)[1]), "r"((a)[2]), "r"((a)[3]), \
          "r"((b)[0]), "r"((b)[1]))

// ---------------------------------------------------------------------------
// HMMA split-bf16 GEMM — EXACT R3 structure (2 buffers, load after compute)
// ---------------------------------------------------------------------------
#define GK     1024
#define BKG    32
#define NKI    (GK / BKG)        // 32
#define TILE_B 8192              // 128 rows * 64B
#define SMEM_G (2 * 4 * TILE_B)  // 65536

__device__ __forceinline__ uint32_t sw_off(int row, int c) {
    int q = c ^ (row & 3) ^ ((row >> 2) & 1);
    return (uint32_t)(row * 64 + q * 16);
}

__device__ __forceinline__ void g_load_stage(
    uint32_t smem_base, int s, int k0, int m0, int n0, int tid,
    const __nv_bfloat16* __restrict__ Ah, const __nv_bfloat16* __restrict__ Al,
    const __nv_bfloat16* __restrict__ Bh, const __nv_bfloat16* __restrict__ Bl)
{
#pragma unroll
    for (int t = 0; t < 4; t++) {
        const __nv_bfloat16* base = (t == 0) ? Ah : (t == 1) ? Al : (t == 2) ? Bh : Bl;
        const int r0 = (t < 2) ? m0 : n0;
        const uint32_t tbase = smem_base + (uint32_t)(s * 4 + t) * TILE_B;
#pragma unroll
        for (int j = 0; j < 2; j++) {
            int idx = tid + j * 256;
            int row = idx >> 2, c = idx & 3;
            const void* src = base + (size_t)(r0 + row) * GK + k0 + c * 8;
            CP_ASYNC16(tbase + sw_off(row, c), src);
        }
    }
}

__global__ __launch_bounds__(256, 1)
void gemm_mma(const __nv_bfloat16* __restrict__ Ah, const __nv_bfloat16* __restrict__ Al,
              const __nv_bfloat16* __restrict__ Bh, const __nv_bfloat16* __restrict__ Bl,
              const float* __restrict__ bias, float* __restrict__ C, int Nn)
{
    extern __shared__ char smem[];
    const uint32_t smem_base = smem_u32(smem);
    const int tid = threadIdx.x;
    const int wid = tid >> 5, lid = tid & 31;
    const int warp_m = wid >> 2, warp_n = wid & 3;
    const int m0 = blockIdx.y * 128, n0 = blockIdx.x * 128;

    float acc[4][4][4];
#pragma unroll
    for (int i = 0; i < 4; i++)
#pragma unroll
        for (int j = 0; j < 4; j++)
#pragma unroll
            for (int f = 0; f < 4; f++) acc[i][j][f] = 0.0f;

    g_load_stage(smem_base, 0, 0,   m0, n0, tid, Ah, Al, Bh, Bl); CP_COMMIT();
    g_load_stage(smem_base, 1, BKG, m0, n0, tid, Ah, Al, Bh, Bl); CP_COMMIT();

    const int a_row = (lid & 15);
    const int a_chk = (lid >> 4) & 1;
    const int b_row = (lid & 7) + (((lid >> 4) & 1) << 3);
    const int b_chk = (lid >> 3) & 1;

    for (int ks = 0; ks < NKI; ks++) {
        if (ks + 1 < NKI) { CP_WAIT(1); } else { CP_WAIT(0); }
        __syncthreads();

        const int buf = ks & 1;
        const uint32_t bAh = smem_base + (uint32_t)(buf * 4 + 0) * TILE_B;
        const uint32_t bAl = smem_base + (uint32_t)(buf * 4 + 1) * TILE_B;
        const uint32_t bBh = smem_base + (uint32_t)(buf * 4 + 2) * TILE_B;
        const uint32_t bBl = smem_base + (uint32_t)(buf * 4 + 3) * TILE_B;

#pragma unroll
        for (int kk = 0; kk < BKG; kk += 16) {
            uint32_t ah[4][4], al[4][4], bh[4][2], bl[4][2];
            const int kc = kk >> 3;
#pragma unroll
            for (int i = 0; i < 4; i++) {
                int r = warp_m * 64 + i * 16 + a_row;
                uint32_t off = sw_off(r, kc + a_chk);
                LDSM_X4(ah[i][0], ah[i][1], ah[i][2], ah[i][3], bAh + off);
                LDSM_X4(al[i][0], al[i][1], al[i][2], al[i][3], bAl + off);
            }
#pragma unroll
            for (int j2 = 0; j2 < 2; j2++) {
                int r = warp_n * 32 + j2 * 16 + b_row;
                uint32_t off = sw_off(r, kc + b_chk);
                LDSM_X4(bh[j2 * 2][0], bh[j2 * 2][1], bh[j2 * 2 + 1][0], bh[j2 * 2 + 1][1],
                        bBh + off);
                LDSM_X4(bl[j2 * 2][0], bl[j2 * 2][1], bl[j2 * 2 + 1][0], bl[j2 * 2 + 1][1],
                        bBl + off);
            }
#pragma unroll
            for (int i = 0; i < 4; i++)
#pragma unroll
                for (int j = 0; j < 4; j++) {
                    MMA16816(acc[i][j], ah[i], bh[j]);
                    MMA16816(acc[i][j], ah[i], bl[j]);
                    MMA16816(acc[i][j], al[i], bh[j]);
                }
        }
        __syncthreads();
        if (ks + 2 < NKI) {
            g_load_stage(smem_base, buf, (ks + 2) * BKG, m0, n0, tid, Ah, Al, Bh, Bl);
            CP_COMMIT();
        }
    }

    const int g = lid >> 2, t = lid & 3;
#pragma unroll
    for (int i = 0; i < 4; i++) {
#pragma unroll
        for (int j = 0; j < 4; j++) {
            int row0 = m0 + warp_m * 64 + i * 16 + g;
            int col  = n0 + warp_n * 32 + j * 8 + 2 * t;
            float b0 = 0.f, b1 = 0.f;
            if (bias) { b0 = bias[col]; b1 = bias[col + 1]; }
            float2 v0 = make_float2(acc[i][j][0] + b0, acc[i][j][1] + b1);
            float2 v1 = make_float2(acc[i][j][2] + b0, acc[i][j][3] + b1);
            *(float2*)(C + (size_t)row0 * Nn + col)       = v0;
            *(float2*)(C + (size_t)(row0 + 8) * Nn + col) = v1;
        }
    }
}

// ---------------------------------------------------------------------------
// fp32 -> bf16 hi/lo split.  4 float4 per thread, 8B packed stores.
// ---------------------------------------------------------------------------
__device__ __forceinline__ void split4(float4 v, uint2* hp, uint2* lp) {
    __nv_bfloat16 h0 = __float2bfloat16_rn(v.x), h1 = __float2bfloat16_rn(v.y);
    __nv_bfloat16 h2 = __float2bfloat16_rn(v.z), h3 = __float2bfloat16_rn(v.w);
    __nv_bfloat16 l0 = __float2bfloat16_rn(v.x - __bfloat162float(h0));
    __nv_bfloat16 l1 = __float2bfloat16_rn(v.y - __bfloat162float(h1));
    __nv_bfloat16 l2 = __float2bfloat16_rn(v.z - __bfloat162float(h2));
    __nv_bfloat16 l3 = __float2bfloat16_rn(v.w - __bfloat162float(h3));
    __nv_bfloat162 hA(h0, h1), hB(h2, h3), lA(l0, l1), lB(l2, l3);
    uint2 hu, lu;
    hu.x = *(uint32_t*)&hA; hu.y = *(uint32_t*)&hB;
    lu.x = *(uint32_t*)&lA; lu.y = *(uint32_t*)&lB;
    *hp = hu; *lp = lu;
}

__global__ __launch_bounds__(256)
void split_bf16(const float4* __restrict__ in, uint2* __restrict__ hi,
                uint2* __restrict__ lo, int n4)
{
    int base = blockIdx.x * 1024 + threadIdx.x;
#pragma unroll
    for (int j = 0; j < 4; j++) {
        int i = base + j * 256;
        if (i < n4) {
            float4 v = in[i];
            split4(v, hi + i, lo + i);
        }
    }
}

// ---------------------------------------------------------------------------
// Global attention over the 32 block-start tokens per (b,h). Runs first,
// writes contribution to g_gadd.
// ---------------------------------------------------------------------------
__global__ __launch_bounds__(32)
void attn_global(const float* __restrict__ Q, const float* __restrict__ Kt,
                 const float* __restrict__ Vt, float* __restrict__ gadd)
{
    __shared__ float Kg[NB * DK];
    __shared__ float Vg[NB * DK];
    const int h = blockIdx.x, b = blockIdx.y;
    const int tid = threadIdx.x;

    for (int i = tid; i < NB * DK; i += 32) {
        int j = i >> 6, d = i & 63;
        size_t r = ((size_t)(b * NTOK + j * BLKSZ)) * DIMV + h * DK + d;
        Kg[i] = Kt[r];
        Vg[i] = Vt[r];
    }
    __syncthreads();

    const int qj = tid;
    const size_t qbase = ((size_t)(b * NTOK + qj * BLKSZ)) * DIMV + h * DK;

    float qv[DK];
#pragma unroll
    for (int d = 0; d < DK; d++) qv[d] = Q[qbase + d];

    float s[NB];
    float m = -1e30f;
#pragma unroll
    for (int k = 0; k < NB; k++) {
        float dot = 0.0f;
#pragma unroll
        for (int d = 0; d < DK; d++) dot = fmaf(qv[d], Kg[k * DK + d], dot);
        s[k] = dot * 0.125f;
        m = fmaxf(m, s[k]);
    }
    float sum = 0.0f;
#pragma unroll
    for (int k = 0; k < NB; k++) { s[k] = __expf(s[k] - m); sum += s[k]; }
    float inv = 1.0f / sum;

    float acc[DK];
#pragma unroll
    for (int d = 0; d < DK; d++) acc[d] = 0.0f;
#pragma unroll
    for (int k = 0; k < NB; k++) {
        float p = s[k];
#pragma unroll
        for (int d = 0; d < DK; d++) acc[d] = fmaf(p, Vg[k * DK + d], acc[d]);
    }
    float* gp = gadd + (((size_t)(b * HEADS + h)) * NB + qj) * DK;
#pragma unroll
    for (int d = 0; d < DK; d++) gp[d] = acc[d] * inv;
}

// ---------------------------------------------------------------------------
// Block attention (proven two-pass) with fused bf16 hi/lo output split.
// ---------------------------------------------------------------------------
#define ATH 160
#define SC_LD 133
#define ATTN_SMEM ((BLKSZ * DK + BLKSZ * SC_LD) * sizeof(float))

__global__ __launch_bounds__(ATH)
void attn_block(const float* __restrict__ Q, const float* __restrict__ Kt,
                const float* __restrict__ Vt, const float* __restrict__ gadd,
                __nv_bfloat16* __restrict__ ohi, __nv_bfloat16* __restrict__ olo)
{
    extern __shared__ float sm[];
    float* Ks = sm;
    float* sc = sm + BLKSZ * DK;

    const int blk = blockIdx.x, h = blockIdx.y, b = blockIdx.z;
    const int tid = threadIdx.x;
    const size_t base = ((size_t)(b * NTOK + blk * BLKSZ)) * DIMV + h * DK;

    for (int i = tid; i < BLKSZ * DK; i += ATH) {
        int kk = i >> 6, d = i & 63;
        Ks[i] = Kt[base + (size_t)kk * DIMV + d];
    }
    __syncthreads();

    const int q = tid;
    float4 qv[16];
    if (q < BLKSZ) {
        const float4* qp = (const float4*)(Q + base + (size_t)q * DIMV);
#pragma unroll
        for (int i = 0; i < 16; i++) qv[i] = qp[i];
        float* srow = sc + q * SC_LD;
        for (int k = 0; k < BLKSZ; k++) {
            const float4* kr = (const float4*)(Ks + k * DK);
            float s = 0.0f;
#pragma unroll
            for (int i = 0; i < 16; i++) {
                float4 kv = kr[i];
                s = fmaf(qv[i].x, kv.x, s); s = fmaf(qv[i].y, kv.y, s);
                s = fmaf(qv[i].z, kv.z, s); s = fmaf(qv[i].w, kv.w, s);
            }
            srow[k] = s * 0.125f;
        }
    }
    __syncthreads();

    for (int i = tid; i < BLKSZ * DK; i += ATH) {
        int kk = i >> 6, d = i & 63;
        Ks[i] = Vt[base + (size_t)kk * DIMV + d];
    }

    float inv = 0.0f;
    if (q < BLKSZ) {
        float* srow = sc + q * SC_LD;
        float m = -1e30f;
        for (int k = 0; k < BLKSZ; k++) m = fmaxf(m, srow[k]);
        float sum = 0.0f;
        for (int k = 0; k < BLKSZ; k++) {
            float e = __expf(srow[k] - m);
            srow[k] = e;
            sum += e;
        }
        inv = 1.0f / sum;
    }
    __syncthreads();

    if (q < BLKSZ) {
        float4 accv[16];
#pragma unroll
        for (int i = 0; i < 16; i++) accv[i] = make_float4(0.f, 0.f, 0.f, 0.f);
        float* srow = sc + q * SC_LD;
        for (int k = 0; k < BLKSZ; k++) {
            float p = srow[k];
            const float4* vr = (const float4*)(Ks + k * DK);
#pragma unroll
            for (int i = 0; i < 16; i++) {
                float4 vv = vr[i];
                accv[i].x = fmaf(p, vv.x, accv[i].x);
                accv[i].y = fmaf(p, vv.y, accv[i].y);
                accv[i].z = fmaf(p, vv.z, accv[i].z);
                accv[i].w = fmaf(p, vv.w, accv[i].w);
            }
        }
        const bool add_g = (q == 0);
        const float* ga = gadd + (((size_t)(b * HEADS + h)) * NB + blk) * DK;
        const size_t obase = base + (size_t)q * DIMV;
#pragma unroll
        for (int i = 0; i < 16; i++) {
            float4 r = accv[i];
            r.x *= inv; r.y *= inv; r.z *= inv; r.w *= inv;
            if (add_g) {
                r.x += ga[4 * i + 0]; r.y += ga[4 * i + 1];
                r.z += ga[4 * i + 2]; r.w += ga[4 * i + 3];
            }
            split4(r, (uint2*)(ohi + obase + 4 * i), (uint2*)(olo + obase + 4 * i));
        }
    }
}

// ---------------------------------------------------------------------------
extern "C" void kernel_launch(void* const* d_in, const int* in_sizes, int n_in,
                              void* d_out, int out_size)
{
    const float* x  = (const float*)d_in[0];
    const float* Wq = (const float*)d_in[1];
    const float* Wk = (const float*)d_in[2];
    const float* Wv = (const float*)d_in[3];
    const float* Wo = (const float*)d_in[4];
    const float* bo = (const float*)d_in[5];
    float* out = (float*)d_out;

    float *q, *k, *v, *gadd;
    __nv_bfloat16 *ah, *al, *wh, *wl, *wh2, *wl2, *wh3, *wl3, *woh, *wol;
    cudaGetSymbolAddress((void**)&q, g_q);
    cudaGetSymbolAddress((void**)&k, g_k);
    cudaGetSymbolAddress((void**)&v, g_v);
    cudaGetSymbolAddress((void**)&gadd, g_gadd);
    cudaGetSymbolAddress((void**)&ah, g_ah);
    cudaGetSymbolAddress((void**)&al, g_al);
    cudaGetSymbolAddress((void**)&wh, g_wh);
    cudaGetSymbolAddress((void**)&wl, g_wl);
    cudaGetSymbolAddress((void**)&wh2, g_wh2);
    cudaGetSymbolAddress((void**)&wl2, g_wl2);
    cudaGetSymbolAddress((void**)&wh3, g_wh3);
    cudaGetSymbolAddress((void**)&wl3, g_wl3);
    cudaGetSymbolAddress((void**)&woh, g_woh);
    cudaGetSymbolAddress((void**)&wol, g_wol);

    cudaFuncSetAttribute(attn_block, cudaFuncAttributeMaxDynamicSharedMemorySize,
                         (int)ATTN_SMEM);
    cudaFuncSetAttribute(gemm_mma, cudaFuncAttributeMaxDynamicSharedMemorySize,
                         SMEM_G);

    const int nX4 = MROWS * DIMV / 4;
    const int nW4 = DIMV * DIMV / 4;
    const int gX = (nX4 + 1023) / 1024;
    const int gW = (nW4 + 1023) / 1024;
    dim3 ggrid(DIMV / 128, MROWS / 128);   // (8, 129)

    // all splits first (so launch #6 = gemm_mma for ncu -s 5 -c 1)
    split_bf16<<<gX, 256>>>((const float4*)x,  (uint2*)ah,  (uint2*)al,  nX4);
    split_bf16<<<gW, 256>>>((const float4*)Wq, (uint2*)wh,  (uint2*)wl,  nW4);
    split_bf16<<<gW, 256>>>((const float4*)Wk, (uint2*)wh2, (uint2*)wl2, nW4);
    split_bf16<<<gW, 256>>>((const float4*)Wv, (uint2*)wh3, (uint2*)wl3, nW4);
    split_bf16<<<gW, 256>>>((const float4*)Wo, (uint2*)woh, (uint2*)wol, nW4);

    gemm_mma<<<ggrid, 256, SMEM_G>>>(ah, al, wh,  wl,  nullptr, q, DIMV);
    gemm_mma<<<ggrid, 256, SMEM_G>>>(ah, al, wh2, wl2, nullptr, k, DIMV);
    gemm_mma<<<ggrid, 256, SMEM_G>>>(ah, al, wh3, wl3, nullptr, v, DIMV);

    attn_global<<<dim3(HEADS, BSZ), 32>>>(q, k, v, gadd);
    // attn_block overwrites ah/al (x split no longer needed) with o's split
    attn_block<<<dim3(NB, HEADS, BSZ), ATH, ATTN_SMEM>>>(q, k, v, gadd, ah, al);

    gemm_mma<<<ggrid, 256, SMEM_G>>>(ah, al, woh, wol, bo, out, DIMV);
}

// round 8
// speedup vs baseline: 1.0897x; 1.0186x over previous
#include <cuda_runtime.h>
#include <cuda_bf16.h>
#include <math.h>
#include <stdint.h>

#define DIMV  1024
#define HEADS 16
#define BLKSZ 129
#define DK    64
#define BSZ   4
#define NB    32
#define NTOK  (BLKSZ * NB)      // 4128
#define MROWS (BSZ * NTOK)      // 16512

// fp32 scratch
__device__ float g_q[(size_t)MROWS * DIMV];
__device__ float g_k[(size_t)MROWS * DIMV];
__device__ float g_v[(size_t)MROWS * DIMV];
__device__ float g_gadd[(size_t)BSZ * HEADS * NB * DK];
// bf16 split scratch
__device__ __nv_bfloat16 g_ah[(size_t)MROWS * DIMV];   // x split, then o split
__device__ __nv_bfloat16 g_al[(size_t)MROWS * DIMV];
__device__ __nv_bfloat16 g_wh[(size_t)DIMV * DIMV];
__device__ __nv_bfloat16 g_wl[(size_t)DIMV * DIMV];
__device__ __nv_bfloat16 g_wh2[(size_t)DIMV * DIMV];
__device__ __nv_bfloat16 g_wl2[(size_t)DIMV * DIMV];
__device__ __nv_bfloat16 g_wh3[(size_t)DIMV * DIMV];
__device__ __nv_bfloat16 g_wl3[(size_t)DIMV * DIMV];
__device__ __nv_bfloat16 g_woh[(size_t)DIMV * DIMV];
__device__ __nv_bfloat16 g_wol[(size_t)DIMV * DIMV];

// ---------------------------------------------------------------------------
// PTX helpers
// ---------------------------------------------------------------------------
__device__ __forceinline__ uint32_t smem_u32(const void* p) {
    uint32_t a;
    asm("{ .reg .u64 t; cvta.to.shared.u64 t, %1; cvt.u32.u64 %0, t; }"
        : "=r"(a) : "l"(p));
    return a;
}
#define CP_ASYNC16(dst, src) \
    asm volatile("cp.async.cg.shared.global [%0], [%1], 16;" :: "r"(dst), "l"(src))
#define CP_COMMIT() asm volatile("cp.async.commit_group;")
#define CP_WAIT(n)  asm volatile("cp.async.wait_group %0;" :: "n"(n))

#define LDSM_X4(r0, r1, r2, r3, addr) \
    asm volatile("ldmatrix.sync.aligned.m8n8.x4.shared.b16 {%0,%1,%2,%3}, [%4];" \
        : "=r"(r0), "=r"(r1), "=r"(r2), "=r"(r3) : "r"(addr))

#define MMA16816(d, a, b) \
    asm volatile("mma.sync.aligned.m16n8k16.row.col.f32.bf16.bf16.f32 " \
        "{%0,%1,%2,%3}, {%4,%5,%6,%7}, {%8,%9}, {%0,%1,%2,%3};" \
        : "+f"((d)[0]), "+f"((d)[1]), "+f"((d)[2]), "+f"((d)[3]) \
        : "r"((a)[0]), "r"((a)[1]), "r"((a)[2]), "r"((a)[3]), \
          "r"((b)[0]), "r"((b)[1]))

// ---------------------------------------------------------------------------
// HMMA split-bf16 GEMM — proven R3 structure (2 buffers, load after compute)
// ---------------------------------------------------------------------------
#define GK     1024
#define BKG    32
#define NKI    (GK / BKG)        // 32
#define TILE_B 8192              // 128 rows * 64B
#define SMEM_G (2 * 4 * TILE_B)  // 65536

__device__ __forceinline__ uint32_t sw_off(int row, int c) {
    int q = c ^ (row & 3) ^ ((row >> 2) & 1);
    return (uint32_t)(row * 64 + q * 16);
}

__device__ __forceinline__ void g_load_stage(
    uint32_t smem_base, int s, int k0, int m0, int n0, int tid,
    const __nv_bfloat16* __restrict__ Ah, const __nv_bfloat16* __restrict__ Al,
    const __nv_bfloat16* __restrict__ Bh, const __nv_bfloat16* __restrict__ Bl)
{
#pragma unroll
    for (int t = 0; t < 4; t++) {
        const __nv_bfloat16* base = (t == 0) ? Ah : (t == 1) ? Al : (t == 2) ? Bh : Bl;
        const int r0 = (t < 2) ? m0 : n0;
        const uint32_t tbase = smem_base + (uint32_t)(s * 4 + t) * TILE_B;
#pragma unroll
        for (int j = 0; j < 2; j++) {
            int idx = tid + j * 256;
            int row = idx >> 2, c = idx & 3;
            const void* src = base + (size_t)(r0 + row) * GK + k0 + c * 8;
            CP_ASYNC16(tbase + sw_off(row, c), src);
        }
    }
}

__global__ __launch_bounds__(256, 1)
void gemm_mma(const __nv_bfloat16* __restrict__ Ah, const __nv_bfloat16* __restrict__ Al,
              const __nv_bfloat16* __restrict__ Bh, const __nv_bfloat16* __restrict__ Bl,
              const float* __restrict__ bias, float* __restrict__ C, int Nn)
{
    extern __shared__ char smem[];
    const uint32_t smem_base = smem_u32(smem);
    const int tid = threadIdx.x;
    const int wid = tid >> 5, lid = tid & 31;
    const int warp_m = wid >> 2, warp_n = wid & 3;
    const int m0 = blockIdx.y * 128, n0 = blockIdx.x * 128;

    float acc[4][4][4];
#pragma unroll
    for (int i = 0; i < 4; i++)
#pragma unroll
        for (int j = 0; j < 4; j++)
#pragma unroll
            for (int f = 0; f < 4; f++) acc[i][j][f] = 0.0f;

    g_load_stage(smem_base, 0, 0,   m0, n0, tid, Ah, Al, Bh, Bl); CP_COMMIT();
    g_load_stage(smem_base, 1, BKG, m0, n0, tid, Ah, Al, Bh, Bl); CP_COMMIT();

    const int a_row = (lid & 15);
    const int a_chk = (lid >> 4) & 1;
    const int b_row = (lid & 7) + (((lid >> 4) & 1) << 3);
    const int b_chk = (lid >> 3) & 1;

    for (int ks = 0; ks < NKI; ks++) {
        if (ks + 1 < NKI) { CP_WAIT(1); } else { CP_WAIT(0); }
        __syncthreads();

        const int buf = ks & 1;
        const uint32_t bAh = smem_base + (uint32_t)(buf * 4 + 0) * TILE_B;
        const uint32_t bAl = smem_base + (uint32_t)(buf * 4 + 1) * TILE_B;
        const uint32_t bBh = smem_base + (uint32_t)(buf * 4 + 2) * TILE_B;
        const uint32_t bBl = smem_base + (uint32_t)(buf * 4 + 3) * TILE_B;

#pragma unroll
        for (int kk = 0; kk < BKG; kk += 16) {
            uint32_t ah[4][4], al[4][4], bh[4][2], bl[4][2];
            const int kc = kk >> 3;
#pragma unroll
            for (int i = 0; i < 4; i++) {
                int r = warp_m * 64 + i * 16 + a_row;
                uint32_t off = sw_off(r, kc + a_chk);
                LDSM_X4(ah[i][0], ah[i][1], ah[i][2], ah[i][3], bAh + off);
                LDSM_X4(al[i][0], al[i][1], al[i][2], al[i][3], bAl + off);
            }
#pragma unroll
            for (int j2 = 0; j2 < 2; j2++) {
                int r = warp_n * 32 + j2 * 16 + b_row;
                uint32_t off = sw_off(r, kc + b_chk);
                LDSM_X4(bh[j2 * 2][0], bh[j2 * 2][1], bh[j2 * 2 + 1][0], bh[j2 * 2 + 1][1],
                        bBh + off);
                LDSM_X4(bl[j2 * 2][0], bl[j2 * 2][1], bl[j2 * 2 + 1][0], bl[j2 * 2 + 1][1],
                        bBl + off);
            }
#pragma unroll
            for (int i = 0; i < 4; i++)
#pragma unroll
                for (int j = 0; j < 4; j++) {
                    MMA16816(acc[i][j], ah[i], bh[j]);
                    MMA16816(acc[i][j], ah[i], bl[j]);
                    MMA16816(acc[i][j], al[i], bh[j]);
                }
        }
        __syncthreads();
        if (ks + 2 < NKI) {
            g_load_stage(smem_base, buf, (ks + 2) * BKG, m0, n0, tid, Ah, Al, Bh, Bl);
            CP_COMMIT();
        }
    }

    const int g = lid >> 2, t = lid & 3;
#pragma unroll
    for (int i = 0; i < 4; i++) {
#pragma unroll
        for (int j = 0; j < 4; j++) {
            int row0 = m0 + warp_m * 64 + i * 16 + g;
            int col  = n0 + warp_n * 32 + j * 8 + 2 * t;
            float b0 = 0.f, b1 = 0.f;
            if (bias) { b0 = bias[col]; b1 = bias[col + 1]; }
            float2 v0 = make_float2(acc[i][j][0] + b0, acc[i][j][1] + b1);
            float2 v1 = make_float2(acc[i][j][2] + b0, acc[i][j][3] + b1);
            *(float2*)(C + (size_t)row0 * Nn + col)       = v0;
            *(float2*)(C + (size_t)(row0 + 8) * Nn + col) = v1;
        }
    }
}

// ---------------------------------------------------------------------------
// fp32 -> bf16 hi/lo split (1 float4 per thread — measured-faster variant)
// ---------------------------------------------------------------------------
__device__ __forceinline__ void split4(float4 v, uint2* hp, uint2* lp) {
    __nv_bfloat16 h0 = __float2bfloat16_rn(v.x), h1 = __float2bfloat16_rn(v.y);
    __nv_bfloat16 h2 = __float2bfloat16_rn(v.z), h3 = __float2bfloat16_rn(v.w);
    __nv_bfloat16 l0 = __float2bfloat16_rn(v.x - __bfloat162float(h0));
    __nv_bfloat16 l1 = __float2bfloat16_rn(v.y - __bfloat162float(h1));
    __nv_bfloat16 l2 = __float2bfloat16_rn(v.z - __bfloat162float(h2));
    __nv_bfloat16 l3 = __float2bfloat16_rn(v.w - __bfloat162float(h3));
    __nv_bfloat162 hA(h0, h1), hB(h2, h3), lA(l0, l1), lB(l2, l3);
    uint2 hu, lu;
    hu.x = *(uint32_t*)&hA; hu.y = *(uint32_t*)&hB;
    lu.x = *(uint32_t*)&lA; lu.y = *(uint32_t*)&lB;
    *hp = hu; *lp = lu;
}

__global__ __launch_bounds__(256)
void split_bf16(const float4* __restrict__ in, uint2* __restrict__ hi,
                uint2* __restrict__ lo, int n4)
{
    int i = blockIdx.x * 256 + threadIdx.x;
    if (i >= n4) return;
    float4 v = in[i];
    split4(v, hi + i, lo + i);
}

// ---------------------------------------------------------------------------
// Global attention over the 32 block-start tokens per (b,h). Runs first,
// writes contribution to g_gadd.
// ---------------------------------------------------------------------------
__global__ __launch_bounds__(32)
void attn_global(const float* __restrict__ Q, const float* __restrict__ Kt,
                 const float* __restrict__ Vt, float* __restrict__ gadd)
{
    __shared__ float Kg[NB * DK];
    __shared__ float Vg[NB * DK];
    const int h = blockIdx.x, b = blockIdx.y;
    const int tid = threadIdx.x;

    for (int i = tid; i < NB * DK; i += 32) {
        int j = i >> 6, d = i & 63;
        size_t r = ((size_t)(b * NTOK + j * BLKSZ)) * DIMV + h * DK + d;
        Kg[i] = Kt[r];
        Vg[i] = Vt[r];
    }
    __syncthreads();

    const int qj = tid;
    const size_t qbase = ((size_t)(b * NTOK + qj * BLKSZ)) * DIMV + h * DK;

    float qv[DK];
#pragma unroll
    for (int d = 0; d < DK; d++) qv[d] = Q[qbase + d];

    float s[NB];
    float m = -1e30f;
#pragma unroll
    for (int k = 0; k < NB; k++) {
        float dot = 0.0f;
#pragma unroll
        for (int d = 0; d < DK; d++) dot = fmaf(qv[d], Kg[k * DK + d], dot);
        s[k] = dot * 0.125f;
        m = fmaxf(m, s[k]);
    }
    float sum = 0.0f;
#pragma unroll
    for (int k = 0; k < NB; k++) { s[k] = __expf(s[k] - m); sum += s[k]; }
    float inv = 1.0f / sum;

    float acc[DK];
#pragma unroll
    for (int d = 0; d < DK; d++) acc[d] = 0.0f;
#pragma unroll
    for (int k = 0; k < NB; k++) {
        float p = s[k];
#pragma unroll
        for (int d = 0; d < DK; d++) acc[d] = fmaf(p, Vg[k * DK + d], acc[d]);
    }
    float* gp = gadd + (((size_t)(b * HEADS + h)) * NB + qj) * DK;
#pragma unroll
    for (int d = 0; d < DK; d++) gp[d] = acc[d] * inv;
}

// ---------------------------------------------------------------------------
// Block attention (two-pass) with fused bf16 hi/lo output split.
// Pass 1 uses 4 independent partial accumulators to break the 64-deep
// FFMA RAW chain (latency exposure /4).
// ---------------------------------------------------------------------------
#define ATH 160
#define SC_LD 133
#define ATTN_SMEM ((BLKSZ * DK + BLKSZ * SC_LD) * sizeof(float))

__global__ __launch_bounds__(ATH)
void attn_block(const float* __restrict__ Q, const float* __restrict__ Kt,
                const float* __restrict__ Vt, const float* __restrict__ gadd,
                __nv_bfloat16* __restrict__ ohi, __nv_bfloat16* __restrict__ olo)
{
    extern __shared__ float sm[];
    float* Ks = sm;
    float* sc = sm + BLKSZ * DK;

    const int blk = blockIdx.x, h = blockIdx.y, b = blockIdx.z;
    const int tid = threadIdx.x;
    const size_t base = ((size_t)(b * NTOK + blk * BLKSZ)) * DIMV + h * DK;

    for (int i = tid; i < BLKSZ * DK; i += ATH) {
        int kk = i >> 6, d = i & 63;
        Ks[i] = Kt[base + (size_t)kk * DIMV + d];
    }
    __syncthreads();

    const int q = tid;
    float4 qv[16];
    if (q < BLKSZ) {
        const float4* qp = (const float4*)(Q + base + (size_t)q * DIMV);
#pragma unroll
        for (int i = 0; i < 16; i++) qv[i] = qp[i];
        float* srow = sc + q * SC_LD;
        for (int k = 0; k < BLKSZ; k++) {
            const float4* kr = (const float4*)(Ks + k * DK);
            float s0 = 0.f, s1 = 0.f, s2 = 0.f, s3 = 0.f;
#pragma unroll
            for (int i = 0; i < 16; i += 4) {
                float4 k0 = kr[i], k1 = kr[i + 1], k2 = kr[i + 2], k3 = kr[i + 3];
                s0 = fmaf(qv[i].x,     k0.x, s0); s0 = fmaf(qv[i].y,     k0.y, s0);
                s0 = fmaf(qv[i].z,     k0.z, s0); s0 = fmaf(qv[i].w,     k0.w, s0);
                s1 = fmaf(qv[i + 1].x, k1.x, s1); s1 = fmaf(qv[i + 1].y, k1.y, s1);
                s1 = fmaf(qv[i + 1].z, k1.z, s1); s1 = fmaf(qv[i + 1].w, k1.w, s1);
                s2 = fmaf(qv[i + 2].x, k2.x, s2); s2 = fmaf(qv[i + 2].y, k2.y, s2);
                s2 = fmaf(qv[i + 2].z, k2.z, s2); s2 = fmaf(qv[i + 2].w, k2.w, s2);
                s3 = fmaf(qv[i + 3].x, k3.x, s3); s3 = fmaf(qv[i + 3].y, k3.y, s3);
                s3 = fmaf(qv[i + 3].z, k3.z, s3); s3 = fmaf(qv[i + 3].w, k3.w, s3);
            }
            srow[k] = ((s0 + s1) + (s2 + s3)) * 0.125f;
        }
    }
    __syncthreads();

    for (int i = tid; i < BLKSZ * DK; i += ATH) {
        int kk = i >> 6, d = i & 63;
        Ks[i] = Vt[base + (size_t)kk * DIMV + d];
    }

    float inv = 0.0f;
    if (q < BLKSZ) {
        float* srow = sc + q * SC_LD;
        float m = -1e30f;
        for (int k = 0; k < BLKSZ; k++) m = fmaxf(m, srow[k]);
        float sum = 0.0f;
        for (int k = 0; k < BLKSZ; k++) {
            float e = __expf(srow[k] - m);
            srow[k] = e;
            sum += e;
        }
        inv = 1.0f / sum;
    }
    __syncthreads();

    if (q < BLKSZ) {
        float4 accv[16];
#pragma unroll
        for (int i = 0; i < 16; i++) accv[i] = make_float4(0.f, 0.f, 0.f, 0.f);
        float* srow = sc + q * SC_LD;
        for (int k = 0; k < BLKSZ; k++) {
            float p = srow[k];
            const float4* vr = (const float4*)(Ks + k * DK);
#pragma unroll
            for (int i = 0; i < 16; i++) {
                float4 vv = vr[i];
                accv[i].x = fmaf(p, vv.x, accv[i].x);
                accv[i].y = fmaf(p, vv.y, accv[i].y);
                accv[i].z = fmaf(p, vv.z, accv[i].z);
                accv[i].w = fmaf(p, vv.w, accv[i].w);
            }
        }
        const bool add_g = (q == 0);
        const float* ga = gadd + (((size_t)(b * HEADS + h)) * NB + blk) * DK;
        const size_t obase = base + (size_t)q * DIMV;
#pragma unroll
        for (int i = 0; i < 16; i++) {
            float4 r = accv[i];
            r.x *= inv; r.y *= inv; r.z *= inv; r.w *= inv;
            if (add_g) {
                r.x += ga[4 * i + 0]; r.y += ga[4 * i + 1];
                r.z += ga[4 * i + 2]; r.w += ga[4 * i + 3];
            }
            split4(r, (uint2*)(ohi + obase + 4 * i), (uint2*)(olo + obase + 4 * i));
        }
    }
}

// ---------------------------------------------------------------------------
extern "C" void kernel_launch(void* const* d_in, const int* in_sizes, int n_in,
                              void* d_out, int out_size)
{
    const float* x  = (const float*)d_in[0];
    const float* Wq = (const float*)d_in[1];
    const float* Wk = (const float*)d_in[2];
    const float* Wv = (const float*)d_in[3];
    const float* Wo = (const float*)d_in[4];
    const float* bo = (const float*)d_in[5];
    float* out = (float*)d_out;

    float *q, *k, *v, *gadd;
    __nv_bfloat16 *ah, *al, *wh, *wl, *wh2, *wl2, *wh3, *wl3, *woh, *wol;
    cudaGetSymbolAddress((void**)&q, g_q);
    cudaGetSymbolAddress((void**)&k, g_k);
    cudaGetSymbolAddress((void**)&v, g_v);
    cudaGetSymbolAddress((void**)&gadd, g_gadd);
    cudaGetSymbolAddress((void**)&ah, g_ah);
    cudaGetSymbolAddress((void**)&al, g_al);
    cudaGetSymbolAddress((void**)&wh, g_wh);
    cudaGetSymbolAddress((void**)&wl, g_wl);
    cudaGetSymbolAddress((void**)&wh2, g_wh2);
    cudaGetSymbolAddress((void**)&wl2, g_wl2);
    cudaGetSymbolAddress((void**)&wh3, g_wh3);
    cudaGetSymbolAddress((void**)&wl3, g_wl3);
    cudaGetSymbolAddress((void**)&woh, g_woh);
    cudaGetSymbolAddress((void**)&wol, g_wol);

    cudaFuncSetAttribute(attn_block, cudaFuncAttributeMaxDynamicSharedMemorySize,
                         (int)ATTN_SMEM);
    cudaFuncSetAttribute(gemm_mma, cudaFuncAttributeMaxDynamicSharedMemorySize,
                         SMEM_G);

    const int nX4 = MROWS * DIMV / 4;
    const int nW4 = DIMV * DIMV / 4;
    dim3 ggrid(DIMV / 128, MROWS / 128);   // (8, 129)

    // launches 1-4: splits; launch 5 = gemm_mma (ncu capture slot)
    split_bf16<<<(nX4 + 255) / 256, 256>>>((const float4*)x,  (uint2*)ah,  (uint2*)al,  nX4);
    split_bf16<<<(nW4 + 255) / 256, 256>>>((const float4*)Wq, (uint2*)wh,  (uint2*)wl,  nW4);
    split_bf16<<<(nW4 + 255) / 256, 256>>>((const float4*)Wk, (uint2*)wh2, (uint2*)wl2, nW4);
    split_bf16<<<(nW4 + 255) / 256, 256>>>((const float4*)Wv, (uint2*)wh3, (uint2*)wl3, nW4);

    gemm_mma<<<ggrid, 256, SMEM_G>>>(ah, al, wh,  wl,  nullptr, q, DIMV);
    gemm_mma<<<ggrid, 256, SMEM_G>>>(ah, al, wh2, wl2, nullptr, k, DIMV);
    gemm_mma<<<ggrid, 256, SMEM_G>>>(ah, al, wh3, wl3, nullptr, v, DIMV);

    attn_global<<<dim3(HEADS, BSZ), 32>>>(q, k, v, gadd);
    attn_block<<<dim3(NB, HEADS, BSZ), ATH, ATTN_SMEM>>>(q, k, v, gadd, ah, al);

    split_bf16<<<(nW4 + 255) / 256, 256>>>((const float4*)Wo, (uint2*)woh, (uint2*)wol, nW4);
    gemm_mma<<<ggrid, 256, SMEM_G>>>(ah, al, woh, wol, bo, out, DIMV);
}

// round 9
// speedup vs baseline: 1.1858x; 1.0883x over previous
#include <cuda_runtime.h>
#include <cuda_bf16.h>
#include <math.h>
#include <stdint.h>

#define DIMV  1024
#define QKVS  3072              // fused qkv row stride
#define HEADS 16
#define BLKSZ 129
#define DK    64
#define BSZ   4
#define NB    32
#define NTOK  (BLKSZ * NB)      // 4128
#define MROWS (BSZ * NTOK)      // 16512

// fp32 scratch
__device__ float g_qkv[(size_t)MROWS * QKVS];           // fused q|k|v
__device__ float g_gadd[(size_t)BSZ * HEADS * NB * DK];
// bf16 split scratch
__device__ __nv_bfloat16 g_ah[(size_t)MROWS * DIMV];    // x split, then o split
__device__ __nv_bfloat16 g_al[(size_t)MROWS * DIMV];
__device__ __nv_bfloat16 g_wqh[(size_t)3 * DIMV * DIMV]; // Wq|Wk|Wv hi
__device__ __nv_bfloat16 g_wql[(size_t)3 * DIMV * DIMV]; // Wq|Wk|Wv lo
__device__ __nv_bfloat16 g_woh[(size_t)DIMV * DIMV];
__device__ __nv_bfloat16 g_wol[(size_t)DIMV * DIMV];

// ---------------------------------------------------------------------------
// PTX helpers
// ---------------------------------------------------------------------------
__device__ __forceinline__ uint32_t smem_u32(const void* p) {
    uint32_t a;
    asm("{ .reg .u64 t; cvta.to.shared.u64 t, %1; cvt.u32.u64 %0, t; }"
        : "=r"(a) : "l"(p));
    return a;
}
#define CP_ASYNC16(dst, src) \
    asm volatile("cp.async.cg.shared.global [%0], [%1], 16;" :: "r"(dst), "l"(src))
#define CP_COMMIT() asm volatile("cp.async.commit_group;")
#define CP_WAIT(n)  asm volatile("cp.async.wait_group %0;" :: "n"(n))

#define LDSM_X4(r0, r1, r2, r3, addr) \
    asm volatile("ldmatrix.sync.aligned.m8n8.x4.shared.b16 {%0,%1,%2,%3}, [%4];" \
        : "=r"(r0), "=r"(r1), "=r"(r2), "=r"(r3) : "r"(addr))

#define MMA16816(d, a, b) \
    asm volatile("mma.sync.aligned.m16n8k16.row.col.f32.bf16.bf16.f32 " \
        "{%0,%1,%2,%3}, {%4,%5,%6,%7}, {%8,%9}, {%0,%1,%2,%3};" \
        : "+f"((d)[0]), "+f"((d)[1]), "+f"((d)[2]), "+f"((d)[3]) \
        : "r"((a)[0]), "r"((a)[1]), "r"((a)[2]), "r"((a)[3]), \
          "r"((b)[0]), "r"((b)[1]))

// ---------------------------------------------------------------------------
// HMMA split-bf16 GEMM — proven R3 mainloop (2 buffers, load after compute)
// ---------------------------------------------------------------------------
#define GK     1024
#define BKG    32
#define NKI    (GK / BKG)        // 32
#define TILE_B 8192              // 128 rows * 64B
#define SMEM_G (2 * 4 * TILE_B)  // 65536

__device__ __forceinline__ uint32_t sw_off(int row, int c) {
    int q = c ^ (row & 3) ^ ((row >> 2) & 1);
    return (uint32_t)(row * 64 + q * 16);
}

__device__ __forceinline__ void g_load_stage(
    uint32_t smem_base, int s, int k0, int m0, int n0, int tid,
    const __nv_bfloat16* __restrict__ Ah, const __nv_bfloat16* __restrict__ Al,
    const __nv_bfloat16* __restrict__ Bh, const __nv_bfloat16* __restrict__ Bl)
{
#pragma unroll
    for (int t = 0; t < 4; t++) {
        const __nv_bfloat16* base = (t == 0) ? Ah : (t == 1) ? Al : (t == 2) ? Bh : Bl;
        const int r0 = (t < 2) ? m0 : n0;
        const uint32_t tbase = smem_base + (uint32_t)(s * 4 + t) * TILE_B;
#pragma unroll
        for (int j = 0; j < 2; j++) {
            int idx = tid + j * 256;
            int row = idx >> 2, c = idx & 3;
            const void* src = base + (size_t)(r0 + row) * GK + k0 + c * 8;
            CP_ASYNC16(tbase + sw_off(row, c), src);
        }
    }
}

__global__ __launch_bounds__(256, 2)
void gemm_mma(const __nv_bfloat16* __restrict__ Ah, const __nv_bfloat16* __restrict__ Al,
              const __nv_bfloat16* __restrict__ Bh, const __nv_bfloat16* __restrict__ Bl,
              const float* __restrict__ bias, float* __restrict__ C, int Nn)
{
    extern __shared__ char smem[];
    const uint32_t smem_base = smem_u32(smem);
    const int tid = threadIdx.x;
    const int wid = tid >> 5, lid = tid & 31;
    const int warp_m = wid >> 2, warp_n = wid & 3;
    const int m0 = blockIdx.y * 128, n0 = blockIdx.x * 128;

    float acc[4][4][4];
#pragma unroll
    for (int i = 0; i < 4; i++)
#pragma unroll
        for (int j = 0; j < 4; j++)
#pragma unroll
            for (int f = 0; f < 4; f++) acc[i][j][f] = 0.0f;

    g_load_stage(smem_base, 0, 0,   m0, n0, tid, Ah, Al, Bh, Bl); CP_COMMIT();
    g_load_stage(smem_base, 1, BKG, m0, n0, tid, Ah, Al, Bh, Bl); CP_COMMIT();

    const int a_row = (lid & 15);
    const int a_chk = (lid >> 4) & 1;
    const int b_row = (lid & 7) + (((lid >> 4) & 1) << 3);
    const int b_chk = (lid >> 3) & 1;

    for (int ks = 0; ks < NKI; ks++) {
        if (ks + 1 < NKI) { CP_WAIT(1); } else { CP_WAIT(0); }
        __syncthreads();

        const int buf = ks & 1;
        const uint32_t bAh = smem_base + (uint32_t)(buf * 4 + 0) * TILE_B;
        const uint32_t bAl = smem_base + (uint32_t)(buf * 4 + 1) * TILE_B;
        const uint32_t bBh = smem_base + (uint32_t)(buf * 4 + 2) * TILE_B;
        const uint32_t bBl = smem_base + (uint32_t)(buf * 4 + 3) * TILE_B;

#pragma unroll
        for (int kk = 0; kk < BKG; kk += 16) {
            uint32_t ah[4][4], al[4][4], bh[4][2], bl[4][2];
            const int kc = kk >> 3;
#pragma unroll
            for (int i = 0; i < 4; i++) {
                int r = warp_m * 64 + i * 16 + a_row;
                uint32_t off = sw_off(r, kc + a_chk);
                LDSM_X4(ah[i][0], ah[i][1], ah[i][2], ah[i][3], bAh + off);
                LDSM_X4(al[i][0], al[i][1], al[i][2], al[i][3], bAl + off);
            }
#pragma unroll
            for (int j2 = 0; j2 < 2; j2++) {
                int r = warp_n * 32 + j2 * 16 + b_row;
                uint32_t off = sw_off(r, kc + b_chk);
                LDSM_X4(bh[j2 * 2][0], bh[j2 * 2][1], bh[j2 * 2 + 1][0], bh[j2 * 2 + 1][1],
                        bBh + off);
                LDSM_X4(bl[j2 * 2][0], bl[j2 * 2][1], bl[j2 * 2 + 1][0], bl[j2 * 2 + 1][1],
                        bBl + off);
            }
#pragma unroll
            for (int i = 0; i < 4; i++)
#pragma unroll
                for (int j = 0; j < 4; j++) {
                    MMA16816(acc[i][j], ah[i], bh[j]);
                    MMA16816(acc[i][j], ah[i], bl[j]);
                    MMA16816(acc[i][j], al[i], bh[j]);
                }
        }
        __syncthreads();
        if (ks + 2 < NKI) {
            g_load_stage(smem_base, buf, (ks + 2) * BKG, m0, n0, tid, Ah, Al, Bh, Bl);
            CP_COMMIT();
        }
    }

    const int g = lid >> 2, t = lid & 3;
#pragma unroll
    for (int i = 0; i < 4; i++) {
#pragma unroll
        for (int j = 0; j < 4; j++) {
            int row0 = m0 + warp_m * 64 + i * 16 + g;
            int col  = n0 + warp_n * 32 + j * 8 + 2 * t;
            float b0 = 0.f, b1 = 0.f;
            if (bias) { b0 = bias[col]; b1 = bias[col + 1]; }
            float2 v0 = make_float2(acc[i][j][0] + b0, acc[i][j][1] + b1);
            float2 v1 = make_float2(acc[i][j][2] + b0, acc[i][j][3] + b1);
            *(float2*)(C + (size_t)row0 * Nn + col)       = v0;
            *(float2*)(C + (size_t)(row0 + 8) * Nn + col) = v1;
        }
    }
}

// ---------------------------------------------------------------------------
// fp32 -> bf16 hi/lo split
// ---------------------------------------------------------------------------
__device__ __forceinline__ void split4(float4 v, uint2* hp, uint2* lp) {
    __nv_bfloat16 h0 = __float2bfloat16_rn(v.x), h1 = __float2bfloat16_rn(v.y);
    __nv_bfloat16 h2 = __float2bfloat16_rn(v.z), h3 = __float2bfloat16_rn(v.w);
    __nv_bfloat16 l0 = __float2bfloat16_rn(v.x - __bfloat162float(h0));
    __nv_bfloat16 l1 = __float2bfloat16_rn(v.y - __bfloat162float(h1));
    __nv_bfloat16 l2 = __float2bfloat16_rn(v.z - __bfloat162float(h2));
    __nv_bfloat16 l3 = __float2bfloat16_rn(v.w - __bfloat162float(h3));
    __nv_bfloat162 hA(h0, h1), hB(h2, h3), lA(l0, l1), lB(l2, l3);
    uint2 hu, lu;
    hu.x = *(uint32_t*)&hA; hu.y = *(uint32_t*)&hB;
    lu.x = *(uint32_t*)&lA; lu.y = *(uint32_t*)&lB;
    *hp = hu; *lp = lu;
}

__global__ __launch_bounds__(256)
void split_bf16(const float4* __restrict__ in, uint2* __restrict__ hi,
                uint2* __restrict__ lo, int n4)
{
    int i = blockIdx.x * 256 + threadIdx.x;
    if (i >= n4) return;
    float4 v = in[i];
    split4(v, hi + i, lo + i);
}

// ---------------------------------------------------------------------------
// Global attention over the 32 block-start tokens per (b,h). Reads fused qkv.
// ---------------------------------------------------------------------------
__global__ __launch_bounds__(32)
void attn_global(const float* __restrict__ QKV, float* __restrict__ gadd)
{
    __shared__ float Kg[NB * DK];
    __shared__ float Vg[NB * DK];
    const int h = blockIdx.x, b = blockIdx.y;
    const int tid = threadIdx.x;

    for (int i = tid; i < NB * DK; i += 32) {
        int j = i >> 6, d = i & 63;
        size_t r = ((size_t)(b * NTOK + j * BLKSZ)) * QKVS + h * DK + d;
        Kg[i] = QKV[r + DIMV];
        Vg[i] = QKV[r + 2 * DIMV];
    }
    __syncthreads();

    const int qj = tid;
    const size_t qbase = ((size_t)(b * NTOK + qj * BLKSZ)) * QKVS + h * DK;

    float qv[DK];
#pragma unroll
    for (int d = 0; d < DK; d++) qv[d] = QKV[qbase + d];

    float s[NB];
    float m = -1e30f;
#pragma unroll
    for (int k = 0; k < NB; k++) {
        float dot = 0.0f;
#pragma unroll
        for (int d = 0; d < DK; d++) dot = fmaf(qv[d], Kg[k * DK + d], dot);
        s[k] = dot * 0.125f;
        m = fmaxf(m, s[k]);
    }
    float sum = 0.0f;
#pragma unroll
    for (int k = 0; k < NB; k++) { s[k] = __expf(s[k] - m); sum += s[k]; }
    float inv = 1.0f / sum;

    float acc[DK];
#pragma unroll
    for (int d = 0; d < DK; d++) acc[d] = 0.0f;
#pragma unroll
    for (int k = 0; k < NB; k++) {
        float p = s[k];
#pragma unroll
        for (int d = 0; d < DK; d++) acc[d] = fmaf(p, Vg[k * DK + d], acc[d]);
    }
    float* gp = gadd + (((size_t)(b * HEADS + h)) * NB + qj) * DK;
#pragma unroll
    for (int d = 0; d < DK; d++) gp[d] = acc[d] * inv;
}

// ---------------------------------------------------------------------------
// Block attention (two-pass, 4-way split pass-1 accumulators) with fused
// bf16 hi/lo output split. Reads fused qkv (stride 3072).
// ---------------------------------------------------------------------------
#define ATH 160
#define SC_LD 133
#define ATTN_SMEM ((BLKSZ * DK + BLKSZ * SC_LD) * sizeof(float))

__global__ __launch_bounds__(ATH)
void attn_block(const float* __restrict__ QKV, const float* __restrict__ gadd,
                __nv_bfloat16* __restrict__ ohi, __nv_bfloat16* __restrict__ olo)
{
    extern __shared__ float sm[];
    float* Ks = sm;
    float* sc = sm + BLKSZ * DK;

    const int blk = blockIdx.x, h = blockIdx.y, b = blockIdx.z;
    const int tid = threadIdx.x;
    const size_t tok0 = (size_t)(b * NTOK + blk * BLKSZ);
    const size_t base = tok0 * QKVS + h * DK;   // q columns; +DIMV = k; +2*DIMV = v

    for (int i = tid; i < BLKSZ * DK; i += ATH) {
        int kk = i >> 6, d = i & 63;
        Ks[i] = QKV[base + (size_t)kk * QKVS + DIMV + d];
    }
    __syncthreads();

    const int q = tid;
    float4 qv[16];
    if (q < BLKSZ) {
        const float4* qp = (const float4*)(QKV + base + (size_t)q * QKVS);
#pragma unroll
        for (int i = 0; i < 16; i++) qv[i] = qp[i];
        float* srow = sc + q * SC_LD;
        for (int k = 0; k < BLKSZ; k++) {
            const float4* kr = (const float4*)(Ks + k * DK);
            float s0 = 0.f, s1 = 0.f, s2 = 0.f, s3 = 0.f;
#pragma unroll
            for (int i = 0; i < 16; i += 4) {
                float4 k0 = kr[i], k1 = kr[i + 1], k2 = kr[i + 2], k3 = kr[i + 3];
                s0 = fmaf(qv[i].x,     k0.x, s0); s0 = fmaf(qv[i].y,     k0.y, s0);
                s0 = fmaf(qv[i].z,     k0.z, s0); s0 = fmaf(qv[i].w,     k0.w, s0);
                s1 = fmaf(qv[i + 1].x, k1.x, s1); s1 = fmaf(qv[i + 1].y, k1.y, s1);
                s1 = fmaf(qv[i + 1].z, k1.z, s1); s1 = fmaf(qv[i + 1].w, k1.w, s1);
                s2 = fmaf(qv[i + 2].x, k2.x, s2); s2 = fmaf(qv[i + 2].y, k2.y, s2);
                s2 = fmaf(qv[i + 2].z, k2.z, s2); s2 = fmaf(qv[i + 2].w, k2.w, s2);
                s3 = fmaf(qv[i + 3].x, k3.x, s3); s3 = fmaf(qv[i + 3].y, k3.y, s3);
                s3 = fmaf(qv[i + 3].z, k3.z, s3); s3 = fmaf(qv[i + 3].w, k3.w, s3);
            }
            srow[k] = ((s0 + s1) + (s2 + s3)) * 0.125f;
        }
    }
    __syncthreads();

    for (int i = tid; i < BLKSZ * DK; i += ATH) {
        int kk = i >> 6, d = i & 63;
        Ks[i] = QKV[base + (size_t)kk * QKVS + 2 * DIMV + d];
    }

    float inv = 0.0f;
    if (q < BLKSZ) {
        float* srow = sc + q * SC_LD;
        float m = -1e30f;
        for (int k = 0; k < BLKSZ; k++) m = fmaxf(m, srow[k]);
        float sum = 0.0f;
        for (int k = 0; k < BLKSZ; k++) {
            float e = __expf(srow[k] - m);
            srow[k] = e;
            sum += e;
        }
        inv = 1.0f / sum;
    }
    __syncthreads();

    if (q < BLKSZ) {
        float4 accv[16];
#pragma unroll
        for (int i = 0; i < 16; i++) accv[i] = make_float4(0.f, 0.f, 0.f, 0.f);
        float* srow = sc + q * SC_LD;
        for (int k = 0; k < BLKSZ; k++) {
            float p = srow[k];
            const float4* vr = (const float4*)(Ks + k * DK);
#pragma unroll
            for (int i = 0; i < 16; i++) {
                float4 vv = vr[i];
                accv[i].x = fmaf(p, vv.x, accv[i].x);
                accv[i].y = fmaf(p, vv.y, accv[i].y);
                accv[i].z = fmaf(p, vv.z, accv[i].z);
                accv[i].w = fmaf(p, vv.w, accv[i].w);
            }
        }
        const bool add_g = (q == 0);
        const float* ga = gadd + (((size_t)(b * HEADS + h)) * NB + blk) * DK;
        const size_t obase = (tok0 + q) * DIMV + h * DK;
#pragma unroll
        for (int i = 0; i < 16; i++) {
            float4 r = accv[i];
            r.x *= inv; r.y *= inv; r.z *= inv; r.w *= inv;
            if (add_g) {
                r.x += ga[4 * i + 0]; r.y += ga[4 * i + 1];
                r.z += ga[4 * i + 2]; r.w += ga[4 * i + 3];
            }
            split4(r, (uint2*)(ohi + obase + 4 * i), (uint2*)(olo + obase + 4 * i));
        }
    }
}

// ---------------------------------------------------------------------------
extern "C" void kernel_launch(void* const* d_in, const int* in_sizes, int n_in,
                              void* d_out, int out_size)
{
    const float* x  = (const float*)d_in[0];
    const float* Wq = (const float*)d_in[1];
    const float* Wk = (const float*)d_in[2];
    const float* Wv = (const float*)d_in[3];
    const float* Wo = (const float*)d_in[4];
    const float* bo = (const float*)d_in[5];
    float* out = (float*)d_out;

    float *qkv, *gadd;
    __nv_bfloat16 *ah, *al, *wqh, *wql, *woh, *wol;
    cudaGetSymbolAddress((void**)&qkv, g_qkv);
    cudaGetSymbolAddress((void**)&gadd, g_gadd);
    cudaGetSymbolAddress((void**)&ah, g_ah);
    cudaGetSymbolAddress((void**)&al, g_al);
    cudaGetSymbolAddress((void**)&wqh, g_wqh);
    cudaGetSymbolAddress((void**)&wql, g_wql);
    cudaGetSymbolAddress((void**)&woh, g_woh);
    cudaGetSymbolAddress((void**)&wol, g_wol);

    cudaFuncSetAttribute(attn_block, cudaFuncAttributeMaxDynamicSharedMemorySize,
                         (int)ATTN_SMEM);
    cudaFuncSetAttribute(gemm_mma, cudaFuncAttributeMaxDynamicSharedMemorySize,
                         SMEM_G);

    const int nX4 = MROWS * DIMV / 4;
    const int nW4 = DIMV * DIMV / 4;
    const size_t wstep = (size_t)DIMV * DIMV;       // elements per weight matrix
    dim3 gq(QKVS / 128, MROWS / 128);               // (24, 129) fused qkv
    dim3 go(DIMV / 128, MROWS / 128);               // (8, 129)  output proj

    split_bf16<<<(nX4 + 255) / 256, 256>>>((const float4*)x,  (uint2*)ah, (uint2*)al, nX4);
    split_bf16<<<(nW4 + 255) / 256, 256>>>((const float4*)Wq,
        (uint2*)wqh, (uint2*)wql, nW4);
    split_bf16<<<(nW4 + 255) / 256, 256>>>((const float4*)Wk,
        (uint2*)(wqh + wstep), (uint2*)(wql + wstep), nW4);
    split_bf16<<<(nW4 + 255) / 256, 256>>>((const float4*)Wv,
        (uint2*)(wqh + 2 * wstep), (uint2*)(wql + 2 * wstep), nW4);

    gemm_mma<<<gq, 256, SMEM_G>>>(ah, al, wqh, wql, nullptr, qkv, QKVS);

    attn_global<<<dim3(HEADS, BSZ), 32>>>(qkv, gadd);
    attn_block<<<dim3(NB, HEADS, BSZ), ATH, ATTN_SMEM>>>(qkv, gadd, ah, al);

    split_bf16<<<(nW4 + 255) / 256, 256>>>((const float4*)Wo, (uint2*)woh, (uint2*)wol, nW4);
    gemm_mma<<<go, 256, SMEM_G>>>(ah, al, woh, wol, bo, out, DIMV);
}